// round 1
// baseline (speedup 1.0000x reference)
#include <cuda_runtime.h>
#include <cstdint>

// Problem dims (fixed by the dataset)
#define M_TOT 32768   // B*S = 8*4096
#define K_TOT 1024    // D
#define N_TOT 1024    // O
#define RNK   16      // LoRA rank
#define NPLANE 5      // 1 shared + 4 tasks
#define XA_COLS 80    // 5 * 16

// Tiling
#define BK 32
#define NSTAGE 3
#define TSTRIDE 36    // BK + 4 pad (keeps 16B alignment: 36*4=144 bytes)
#define BM 128
#define BN 128
#define XAS_STRIDE 84 // 80 + 4 pad (84*4 = 336 bytes, 16B aligned)
#define BEP_STRIDE 20 // 16 + 4 pad (80 bytes, 16B aligned)
#define X_BM 128
#define X_BN 80

// Scratch for XA = x @ [A_sh; A_tasks]^T  -> [M_TOT, 80]
__device__ float g_xa[(size_t)M_TOT * XA_COLS];

__device__ __forceinline__ unsigned f2tf(float f) {
    unsigned u;
    asm("cvt.rna.tf32.f32 %0, %1;" : "=r"(u) : "f"(f));
    return u;
}

__device__ __forceinline__ void mma8(float c[4], unsigned a0, unsigned a1, unsigned a2,
                                     unsigned a3, unsigned b0, unsigned b1) {
    asm volatile(
        "mma.sync.aligned.m16n8k8.row.col.f32.tf32.tf32.f32 "
        "{%0,%1,%2,%3},{%4,%5,%6,%7},{%8,%9},{%0,%1,%2,%3};"
        : "+f"(c[0]), "+f"(c[1]), "+f"(c[2]), "+f"(c[3])
        : "r"(a0), "r"(a1), "r"(a2), "r"(a3), "r"(b0), "r"(b1));
}

__device__ __forceinline__ unsigned sptr(const void* p) {
    return (unsigned)__cvta_generic_to_shared(p);
}
#define CP16(d, s) asm volatile("cp.async.cg.shared.global [%0], [%1], 16;" ::"r"(d), "l"(s))
#define CPC() asm volatile("cp.async.commit_group;")
#define CPW(n) asm volatile("cp.async.wait_group %0;" ::"n"(n))

// ---------------------------------------------------------------------------
// Kernel 1: XA[m, 0:16]    = x @ A_sh^T
//           XA[m, 16+16t+r]= x @ A_tasks[t]^T
// [32768,1024] x [1024,80] tf32 GEMM. 8 warps as 4x2, warp tile 32x40.
// ---------------------------------------------------------------------------
__global__ void __launch_bounds__(256) xa_kernel(const float* __restrict__ x,
                                                 const float* __restrict__ A_sh,
                                                 const float* __restrict__ A_tasks) {
    extern __shared__ float sm[];
    float* As = sm;                                 // NSTAGE * X_BM * TSTRIDE
    float* Bs = sm + NSTAGE * X_BM * TSTRIDE;       // NSTAGE * X_BN * TSTRIDE

    const int tid = threadIdx.x;
    const int lane = tid & 31, wid = tid >> 5;
    const int warpM = wid >> 1, warpN = wid & 1;    // 4 x 2
    const int bm = blockIdx.x;
    const int g = lane >> 2, tg = lane & 3;

    float acc[2][5][4];
#pragma unroll
    for (int i = 0; i < 2; i++)
#pragma unroll
        for (int j = 0; j < 5; j++)
#pragma unroll
            for (int q = 0; q < 4; q++) acc[i][j][q] = 0.f;

    auto load_stage = [&](int buf, int kt) {
        const float* asrc = x + (size_t)(bm * X_BM) * K_TOT + kt * BK;
        float* ad = As + buf * X_BM * TSTRIDE;
#pragma unroll
        for (int i = 0; i < 4; i++) {
            int idx = tid + i * 256;
            int r = idx >> 3, v = idx & 7;
            CP16(sptr(ad + r * TSTRIDE + v * 4), asrc + (size_t)r * K_TOT + v * 4);
        }
        float* bd = Bs + buf * X_BN * TSTRIDE;
        for (int idx = tid; idx < X_BN * 8; idx += 256) {
            int r = idx >> 3, v = idx & 7;
            const float* src =
                (r < RNK) ? (A_sh + (size_t)r * K_TOT + kt * BK + v * 4)
                          : (A_tasks + (size_t)(r - RNK) * K_TOT + kt * BK + v * 4);
            CP16(sptr(bd + r * TSTRIDE + v * 4), src);
        }
    };

    load_stage(0, 0);
    CPC();
    load_stage(1, 1);
    CPC();

    const int KT = K_TOT / BK;
    for (int kt = 0; kt < KT; kt++) {
        CPW(1);
        __syncthreads();
        if (kt + 2 < KT) load_stage((kt + 2) % NSTAGE, kt + 2);
        CPC();
        const float* A = As + (kt % NSTAGE) * X_BM * TSTRIDE;
        const float* B = Bs + (kt % NSTAGE) * X_BN * TSTRIDE;
#pragma unroll
        for (int kk = 0; kk < BK; kk += 8) {
            unsigned af[2][4], bf[5][2];
#pragma unroll
            for (int mt = 0; mt < 2; mt++) {
                int r0 = warpM * 32 + mt * 16 + g;
                af[mt][0] = f2tf(A[r0 * TSTRIDE + kk + tg]);
                af[mt][1] = f2tf(A[(r0 + 8) * TSTRIDE + kk + tg]);
                af[mt][2] = f2tf(A[r0 * TSTRIDE + kk + tg + 4]);
                af[mt][3] = f2tf(A[(r0 + 8) * TSTRIDE + kk + tg + 4]);
            }
#pragma unroll
            for (int nt = 0; nt < 5; nt++) {
                int n = warpN * 40 + nt * 8 + g;
                bf[nt][0] = f2tf(B[n * TSTRIDE + kk + tg]);
                bf[nt][1] = f2tf(B[n * TSTRIDE + kk + tg + 4]);
            }
#pragma unroll
            for (int mt = 0; mt < 2; mt++)
#pragma unroll
                for (int nt = 0; nt < 5; nt++)
                    mma8(acc[mt][nt], af[mt][0], af[mt][1], af[mt][2], af[mt][3],
                         bf[nt][0], bf[nt][1]);
        }
    }

#pragma unroll
    for (int mt = 0; mt < 2; mt++) {
#pragma unroll
        for (int nt = 0; nt < 5; nt++) {
            int row = bm * X_BM + warpM * 32 + mt * 16 + g;
            int col = warpN * 40 + nt * 8 + tg * 2;
            *(float2*)&g_xa[(size_t)row * XA_COLS + col] =
                make_float2(acc[mt][nt][0], acc[mt][nt][1]);
            *(float2*)&g_xa[(size_t)(row + 8) * XA_COLS + col] =
                make_float2(acc[mt][nt][2], acc[mt][nt][3]);
        }
    }
}

// ---------------------------------------------------------------------------
// Kernel 2: main fused GEMM.
//   acc = x @ W^T (K=1024, tf32 tensor cores)
//   per plane p: delta_p = XA[:, 16p:16p+16] @ Bp^T  (2 extra mma k-steps)
//   out[p] = acc + bias + scale_p * delta_p
// 8 warps as 2x4, warp tile 64x32.
// ---------------------------------------------------------------------------
__global__ void __launch_bounds__(256, 1) main_kernel(
    const float* __restrict__ x, const float* __restrict__ W,
    const float* __restrict__ bias, const float* __restrict__ B_sh,
    const float* __restrict__ B_tasks, const float* __restrict__ scales,
    float* __restrict__ out) {
    extern __shared__ float sm[];
    float* As = sm;                                  // NSTAGE * BM * TSTRIDE
    float* Bs = As + NSTAGE * BM * TSTRIDE;          // NSTAGE * BN * TSTRIDE
    float* XAs = Bs + NSTAGE * BN * TSTRIDE;         // BM * XAS_STRIDE
    float* Bep = XAs + BM * XAS_STRIDE;              // NPLANE * BN * BEP_STRIDE

    const int tid = threadIdx.x;
    const int lane = tid & 31, wid = tid >> 5;
    const int warpM = wid >> 2, warpN = wid & 3;     // 2 x 4
    const int bn = blockIdx.x, bm = blockIdx.y;
    const int g = lane >> 2, tg = lane & 3;

    float acc[4][4][4];
#pragma unroll
    for (int i = 0; i < 4; i++)
#pragma unroll
        for (int j = 0; j < 4; j++)
#pragma unroll
            for (int q = 0; q < 4; q++) acc[i][j][q] = 0.f;

    // Epilogue tiles: issued into async group 0, complete well before epilogue.
    for (int idx = tid; idx < BM * (XA_COLS / 4); idx += 256) {
        int r = idx / (XA_COLS / 4), v = idx % (XA_COLS / 4);
        CP16(sptr(XAs + r * XAS_STRIDE + v * 4),
             g_xa + (size_t)(bm * BM + r) * XA_COLS + v * 4);
    }
    for (int idx = tid; idx < NPLANE * BN * 4; idx += 256) {
        int p = idx / (BN * 4), rem = idx % (BN * 4);
        int n = rem >> 2, v = rem & 3;
        const float* src =
            (p == 0) ? (B_sh + (size_t)(bn * BN + n) * RNK + v * 4)
                     : (B_tasks + ((size_t)(p - 1) * N_TOT + bn * BN + n) * RNK + v * 4);
        CP16(sptr(Bep + (p * BN + n) * BEP_STRIDE + v * 4), src);
    }

    auto load_stage = [&](int buf, int kt) {
        const float* asrc = x + (size_t)(bm * BM) * K_TOT + kt * BK;
        const float* bsrc = W + (size_t)(bn * BN) * K_TOT + kt * BK;
        float* ad = As + buf * BM * TSTRIDE;
        float* bd = Bs + buf * BN * TSTRIDE;
#pragma unroll
        for (int i = 0; i < 4; i++) {
            int idx = tid + i * 256;
            int r = idx >> 3, v = idx & 7;
            CP16(sptr(ad + r * TSTRIDE + v * 4), asrc + (size_t)r * K_TOT + v * 4);
        }
#pragma unroll
        for (int i = 0; i < 4; i++) {
            int idx = tid + i * 256;
            int r = idx >> 3, v = idx & 7;
            CP16(sptr(bd + r * TSTRIDE + v * 4), bsrc + (size_t)r * K_TOT + v * 4);
        }
    };

    load_stage(0, 0);
    CPC();   // group 0: epilogue tiles + stage 0
    load_stage(1, 1);
    CPC();   // group 1: stage 1

    const int KT = K_TOT / BK;
    for (int kt = 0; kt < KT; kt++) {
        CPW(1);
        __syncthreads();
        if (kt + 2 < KT) load_stage((kt + 2) % NSTAGE, kt + 2);
        CPC();
        const float* A = As + (kt % NSTAGE) * BM * TSTRIDE;
        const float* B = Bs + (kt % NSTAGE) * BN * TSTRIDE;
#pragma unroll
        for (int kk = 0; kk < BK; kk += 8) {
            unsigned af[4][4], bf[4][2];
#pragma unroll
            for (int mt = 0; mt < 4; mt++) {
                int r0 = warpM * 64 + mt * 16 + g;
                af[mt][0] = f2tf(A[r0 * TSTRIDE + kk + tg]);
                af[mt][1] = f2tf(A[(r0 + 8) * TSTRIDE + kk + tg]);
                af[mt][2] = f2tf(A[r0 * TSTRIDE + kk + tg + 4]);
                af[mt][3] = f2tf(A[(r0 + 8) * TSTRIDE + kk + tg + 4]);
            }
#pragma unroll
            for (int nt = 0; nt < 4; nt++) {
                int n = warpN * 32 + nt * 8 + g;
                bf[nt][0] = f2tf(B[n * TSTRIDE + kk + tg]);
                bf[nt][1] = f2tf(B[n * TSTRIDE + kk + tg + 4]);
            }
#pragma unroll
            for (int mt = 0; mt < 4; mt++)
#pragma unroll
                for (int nt = 0; nt < 4; nt++)
                    mma8(acc[mt][nt], af[mt][0], af[mt][1], af[mt][2], af[mt][3],
                         bf[nt][0], bf[nt][1]);
        }
    }

    // ---- Epilogue: per-plane rank-16 tensor-core GEMM + bias + store ----
    float scl[NPLANE];
    scl[0] = 1.f;
#pragma unroll
    for (int p = 1; p < NPLANE; p++) scl[p] = __ldg(&scales[p - 1]);

    float bv0[4], bv1[4];
#pragma unroll
    for (int nt = 0; nt < 4; nt++) {
        int c = bn * BN + warpN * 32 + nt * 8 + tg * 2;
        bv0[nt] = __ldg(&bias[c]);
        bv1[nt] = __ldg(&bias[c + 1]);
    }

#pragma unroll
    for (int p = 0; p < NPLANE; p++) {
        float d[4][4][4];
#pragma unroll
        for (int i = 0; i < 4; i++)
#pragma unroll
            for (int j = 0; j < 4; j++)
#pragma unroll
                for (int q = 0; q < 4; q++) d[i][j][q] = 0.f;

#pragma unroll
        for (int kk = 0; kk < RNK; kk += 8) {
            unsigned af[4][4], bf[4][2];
#pragma unroll
            for (int mt = 0; mt < 4; mt++) {
                int r0 = warpM * 64 + mt * 16 + g;
                int c = p * RNK + kk + tg;
                af[mt][0] = f2tf(XAs[r0 * XAS_STRIDE + c]);
                af[mt][1] = f2tf(XAs[(r0 + 8) * XAS_STRIDE + c]);
                af[mt][2] = f2tf(XAs[r0 * XAS_STRIDE + c + 4]);
                af[mt][3] = f2tf(XAs[(r0 + 8) * XAS_STRIDE + c + 4]);
            }
#pragma unroll
            for (int nt = 0; nt < 4; nt++) {
                int n = warpN * 32 + nt * 8 + g;
                bf[nt][0] = f2tf(Bep[(p * BN + n) * BEP_STRIDE + kk + tg]);
                bf[nt][1] = f2tf(Bep[(p * BN + n) * BEP_STRIDE + kk + tg + 4]);
            }
#pragma unroll
            for (int mt = 0; mt < 4; mt++)
#pragma unroll
                for (int nt = 0; nt < 4; nt++)
                    mma8(d[mt][nt], af[mt][0], af[mt][1], af[mt][2], af[mt][3],
                         bf[nt][0], bf[nt][1]);
        }

        float* op = out + (size_t)p * M_TOT * N_TOT;
        float s = scl[p];
#pragma unroll
        for (int mt = 0; mt < 4; mt++) {
#pragma unroll
            for (int nt = 0; nt < 4; nt++) {
                int row = bm * BM + warpM * 64 + mt * 16 + g;
                int col = bn * BN + warpN * 32 + nt * 8 + tg * 2;
                float2 v0 = make_float2(acc[mt][nt][0] + s * d[mt][nt][0] + bv0[nt],
                                        acc[mt][nt][1] + s * d[mt][nt][1] + bv1[nt]);
                float2 v1 = make_float2(acc[mt][nt][2] + s * d[mt][nt][2] + bv0[nt],
                                        acc[mt][nt][3] + s * d[mt][nt][3] + bv1[nt]);
                __stcs((float2*)&op[(size_t)row * N_TOT + col], v0);
                __stcs((float2*)&op[(size_t)(row + 8) * N_TOT + col], v1);
            }
        }
    }
}

// ---------------------------------------------------------------------------
extern "C" void kernel_launch(void* const* d_in, const int* in_sizes, int n_in,
                              void* d_out, int out_size) {
    const float* x = (const float*)d_in[0];
    const float* W = (const float*)d_in[1];
    const float* b = (const float*)d_in[2];
    const float* A_sh = (const float*)d_in[3];
    const float* B_sh = (const float*)d_in[4];
    const float* A_tasks = (const float*)d_in[5];
    const float* B_tasks = (const float*)d_in[6];
    const float* scales = (const float*)d_in[7];
    float* out = (float*)d_out;

    const int xa_smem = (NSTAGE * (X_BM + X_BN) * TSTRIDE) * 4;               // 89856 B
    const int main_smem =
        (NSTAGE * (BM + BN) * TSTRIDE + BM * XAS_STRIDE + NPLANE * BN * BEP_STRIDE) * 4;  // 204800 B

    cudaFuncSetAttribute(xa_kernel, cudaFuncAttributeMaxDynamicSharedMemorySize, xa_smem);
    cudaFuncSetAttribute(main_kernel, cudaFuncAttributeMaxDynamicSharedMemorySize, main_smem);

    xa_kernel<<<M_TOT / X_BM, 256, xa_smem>>>(x, A_sh, A_tasks);
    main_kernel<<<dim3(N_TOT / BN, M_TOT / BM), 256, main_smem>>>(x, W, b, B_sh, B_tasks,
                                                                  scales, out);
    (void)in_sizes; (void)n_in; (void)out_size;
}

// round 4
// speedup vs baseline: 1.0440x; 1.0440x over previous
#include <cuda_runtime.h>
#include <cstdint>

// Problem dims
#define M_TOT 32768
#define K_TOT 1024
#define N_TOT 1024
#define RNK   16
#define NPLANE 5
#define XA_COLS 80

// ---------------- scratch ----------------
__device__ float g_xa[(size_t)M_TOT * XA_COLS];   // XA = x @ [A_sh; A_tasks]^T
__device__ float g_wr[(size_t)N_TOT * K_TOT];     // W rounded to tf32 (rna)
__device__ float g_ar[(size_t)XA_COLS * K_TOT];   // [A_sh; A_tasks] rounded to tf32

__device__ __forceinline__ unsigned f2tf(float f) {
    unsigned u;
    asm("cvt.rna.tf32.f32 %0, %1;" : "=r"(u) : "f"(f));
    return u;
}
__device__ __forceinline__ uint32_t smem_u32(const void* p) {
    return (uint32_t)__cvta_generic_to_shared(p);
}
#define CP16(d, s) asm volatile("cp.async.cg.shared.global [%0], [%1], 16;" ::"r"(d), "l"(s))
#define CPC() asm volatile("cp.async.commit_group;")
#define CPW(n) asm volatile("cp.async.wait_group %0;" ::"n"(n))

__device__ __forceinline__ void mma8(float c[4], unsigned a0, unsigned a1, unsigned a2,
                                     unsigned a3, unsigned b0, unsigned b1) {
    asm volatile(
        "mma.sync.aligned.m16n8k8.row.col.f32.tf32.tf32.f32 "
        "{%0,%1,%2,%3},{%4,%5,%6,%7},{%8,%9},{%0,%1,%2,%3};"
        : "+f"(c[0]), "+f"(c[1]), "+f"(c[2]), "+f"(c[3])
        : "r"(a0), "r"(a1), "r"(a2), "r"(a3), "r"(b0), "r"(b1));
}

// ---------------------------------------------------------------------------
// Pre-round W and A matrices to tf32 (rna). Lets the hot loops skip cvt:
// HMMA-tf32 truncates operand mantissas, so pre-rounded operands behave as
// if rounded-to-nearest; x is left raw (truncation, ~1e-4 bias, in budget).
// ---------------------------------------------------------------------------
__global__ void round_w_kernel(const float* __restrict__ W) {
    int i = blockIdx.x * 1024 + threadIdx.x;
#pragma unroll
    for (int j = 0; j < 4; j++)
        g_wr[i + j * 256] = __uint_as_float(f2tf(W[i + j * 256]));
}
__global__ void round_a_kernel(const float* __restrict__ A_sh,
                               const float* __restrict__ A_tasks) {
    int i = blockIdx.x * 256 + threadIdx.x;   // 320 blocks -> 81920 elems
    float v = (i < RNK * K_TOT) ? A_sh[i] : A_tasks[i - RNK * K_TOT];
    g_ar[i] = __uint_as_float(f2tf(v));
}

// ---------------------------------------------------------------------------
// Kernel 1: XA = x @ [A_sh; A_tasks]^T   [32768,1024]x[1024,80]
// 8 warps as 4x2, warp tile 32x40, occupancy 2. No cvt in hot loop.
// ---------------------------------------------------------------------------
#define BKX 32
#define TSTRIDE 36
#define X_BM 128
#define X_BN 80

__global__ void __launch_bounds__(256, 2) xa_kernel(const float* __restrict__ x) {
    extern __shared__ float sm[];
    float* As = sm;
    float* Bs = sm + 3 * X_BM * TSTRIDE;

    const int tid = threadIdx.x;
    const int lane = tid & 31, wid = tid >> 5;
    const int warpM = wid >> 1, warpN = wid & 1;
    const int bm = blockIdx.x;
    const int g = lane >> 2, tg = lane & 3;

    float acc[2][5][4];
#pragma unroll
    for (int i = 0; i < 2; i++)
#pragma unroll
        for (int j = 0; j < 5; j++)
#pragma unroll
            for (int q = 0; q < 4; q++) acc[i][j][q] = 0.f;

    auto load_stage = [&](int buf, int kt) {
        const float* asrc = x + (size_t)(bm * X_BM) * K_TOT + kt * BKX;
        float* ad = As + buf * X_BM * TSTRIDE;
#pragma unroll
        for (int i = 0; i < 4; i++) {
            int idx = tid + i * 256;
            int r = idx >> 3, v = idx & 7;
            CP16(smem_u32(ad + r * TSTRIDE + v * 4), asrc + (size_t)r * K_TOT + v * 4);
        }
        float* bd = Bs + buf * X_BN * TSTRIDE;
        for (int idx = tid; idx < X_BN * 8; idx += 256) {
            int r = idx >> 3, v = idx & 7;
            CP16(smem_u32(bd + r * TSTRIDE + v * 4),
                 g_ar + (size_t)r * K_TOT + kt * BKX + v * 4);
        }
    };

    load_stage(0, 0); CPC();
    load_stage(1, 1); CPC();

    const int KT = K_TOT / BKX;
    for (int kt = 0; kt < KT; kt++) {
        CPW(1);
        __syncthreads();
        if (kt + 2 < KT) load_stage((kt + 2) % 3, kt + 2);
        CPC();
        const float* A = As + (kt % 3) * X_BM * TSTRIDE;
        const float* B = Bs + (kt % 3) * X_BN * TSTRIDE;
#pragma unroll
        for (int kk = 0; kk < BKX; kk += 8) {
            unsigned af[2][4], bf[5][2];
#pragma unroll
            for (int mt = 0; mt < 2; mt++) {
                int r0 = warpM * 32 + mt * 16 + g;
                af[mt][0] = __float_as_uint(A[r0 * TSTRIDE + kk + tg]);
                af[mt][1] = __float_as_uint(A[(r0 + 8) * TSTRIDE + kk + tg]);
                af[mt][2] = __float_as_uint(A[r0 * TSTRIDE + kk + tg + 4]);
                af[mt][3] = __float_as_uint(A[(r0 + 8) * TSTRIDE + kk + tg + 4]);
            }
#pragma unroll
            for (int nt = 0; nt < 5; nt++) {
                int n = warpN * 40 + nt * 8 + g;
                bf[nt][0] = __float_as_uint(B[n * TSTRIDE + kk + tg]);
                bf[nt][1] = __float_as_uint(B[n * TSTRIDE + kk + tg + 4]);
            }
#pragma unroll
            for (int mt = 0; mt < 2; mt++)
#pragma unroll
                for (int nt = 0; nt < 5; nt++)
                    mma8(acc[mt][nt], af[mt][0], af[mt][1], af[mt][2], af[mt][3],
                         bf[nt][0], bf[nt][1]);
        }
    }

#pragma unroll
    for (int mt = 0; mt < 2; mt++)
#pragma unroll
        for (int nt = 0; nt < 5; nt++) {
            int row = bm * X_BM + warpM * 32 + mt * 16 + g;
            int col = warpN * 40 + nt * 8 + tg * 2;
            *(float2*)&g_xa[(size_t)row * XA_COLS + col] =
                make_float2(acc[mt][nt][0], acc[mt][nt][1]);
            *(float2*)&g_xa[(size_t)(row + 8) * XA_COLS + col] =
                make_float2(acc[mt][nt][2], acc[mt][nt][3]);
        }
}

// ---------------------------------------------------------------------------
// Kernel 2: main fused GEMM, mma.sync tf32, 512 threads (16 warps as 4x4,
// warp tile 32x32). No cvt in hot loop. Epilogue: rank-16 per-plane delta
// GEMM from smem + bias + streaming stores.
// ---------------------------------------------------------------------------
#define BK 32
#define BM 128
#define BN 128
#define XAS_STRIDE 84
#define BEP_STRIDE 20
#define NTHR 512

__global__ void __launch_bounds__(NTHR, 1) main_kernel(
    const float* __restrict__ x, const float* __restrict__ bias,
    const float* __restrict__ B_sh, const float* __restrict__ B_tasks,
    const float* __restrict__ scales, float* __restrict__ out) {
    extern __shared__ float sm[];
    float* As = sm;                                  // 3 * BM * TSTRIDE
    float* Bs = As + 3 * BM * TSTRIDE;               // 3 * BN * TSTRIDE
    float* XAs = Bs + 3 * BN * TSTRIDE;              // BM * XAS_STRIDE
    float* Bep = XAs + BM * XAS_STRIDE;              // NPLANE * BN * BEP_STRIDE

    const int tid = threadIdx.x;
    const int lane = tid & 31, wid = tid >> 5;
    const int warpM = wid >> 2, warpN = wid & 3;     // 4 x 4
    const int bn = blockIdx.x, bm = blockIdx.y;
    const int g = lane >> 2, tg = lane & 3;

    float acc[2][4][4];
#pragma unroll
    for (int i = 0; i < 2; i++)
#pragma unroll
        for (int j = 0; j < 4; j++)
#pragma unroll
            for (int q = 0; q < 4; q++) acc[i][j][q] = 0.f;

    // Epilogue tiles into async group 0 (complete long before epilogue).
    for (int idx = tid; idx < BM * (XA_COLS / 4); idx += NTHR) {
        int r = idx / (XA_COLS / 4), v = idx % (XA_COLS / 4);
        CP16(smem_u32(XAs + r * XAS_STRIDE + v * 4),
             g_xa + (size_t)(bm * BM + r) * XA_COLS + v * 4);
    }
    for (int idx = tid; idx < NPLANE * BN * 4; idx += NTHR) {
        int p = idx / (BN * 4), rem = idx % (BN * 4);
        int n = rem >> 2, v = rem & 3;
        const float* src =
            (p == 0) ? (B_sh + (size_t)(bn * BN + n) * RNK + v * 4)
                     : (B_tasks + ((size_t)(p - 1) * N_TOT + bn * BN + n) * RNK + v * 4);
        CP16(smem_u32(Bep + (p * BN + n) * BEP_STRIDE + v * 4), src);
    }

    auto load_stage = [&](int buf, int kt) {
        const float* asrc = x + (size_t)(bm * BM) * K_TOT + kt * BK;
        const float* bsrc = g_wr + (size_t)(bn * BN) * K_TOT + kt * BK;
        float* ad = As + buf * BM * TSTRIDE;
        float* bd = Bs + buf * BN * TSTRIDE;
#pragma unroll
        for (int i = 0; i < 2; i++) {
            int idx = tid + i * NTHR;
            int r = idx >> 3, v = idx & 7;
            CP16(smem_u32(ad + r * TSTRIDE + v * 4), asrc + (size_t)r * K_TOT + v * 4);
            CP16(smem_u32(bd + r * TSTRIDE + v * 4), bsrc + (size_t)r * K_TOT + v * 4);
        }
    };

    load_stage(0, 0); CPC();   // group: epi tiles + stage 0
    load_stage(1, 1); CPC();

    const int KT = K_TOT / BK;
    for (int kt = 0; kt < KT; kt++) {
        CPW(1);
        __syncthreads();
        if (kt + 2 < KT) load_stage((kt + 2) % 3, kt + 2);
        CPC();
        const float* A = As + (kt % 3) * BM * TSTRIDE;
        const float* B = Bs + (kt % 3) * BN * TSTRIDE;
#pragma unroll
        for (int kk = 0; kk < BK; kk += 8) {
            unsigned af[2][4], bf[4][2];
#pragma unroll
            for (int mt = 0; mt < 2; mt++) {
                int r0 = warpM * 32 + mt * 16 + g;
                af[mt][0] = __float_as_uint(A[r0 * TSTRIDE + kk + tg]);
                af[mt][1] = __float_as_uint(A[(r0 + 8) * TSTRIDE + kk + tg]);
                af[mt][2] = __float_as_uint(A[r0 * TSTRIDE + kk + tg + 4]);
                af[mt][3] = __float_as_uint(A[(r0 + 8) * TSTRIDE + kk + tg + 4]);
            }
#pragma unroll
            for (int nt = 0; nt < 4; nt++) {
                int n = warpN * 32 + nt * 8 + g;
                bf[nt][0] = __float_as_uint(B[n * TSTRIDE + kk + tg]);
                bf[nt][1] = __float_as_uint(B[n * TSTRIDE + kk + tg + 4]);
            }
#pragma unroll
            for (int mt = 0; mt < 2; mt++)
#pragma unroll
                for (int nt = 0; nt < 4; nt++)
                    mma8(acc[mt][nt], af[mt][0], af[mt][1], af[mt][2], af[mt][3],
                         bf[nt][0], bf[nt][1]);
        }
    }

    CPW(0);
    __syncthreads();

    // ---- Epilogue ----
    float scl[NPLANE];
    scl[0] = 1.f;
#pragma unroll
    for (int p = 1; p < NPLANE; p++) scl[p] = __ldg(&scales[p - 1]);

    float bv0[4], bv1[4];
#pragma unroll
    for (int nt = 0; nt < 4; nt++) {
        int c = bn * BN + warpN * 32 + nt * 8 + tg * 2;
        bv0[nt] = __ldg(&bias[c]);
        bv1[nt] = __ldg(&bias[c + 1]);
    }

#pragma unroll
    for (int p = 0; p < NPLANE; p++) {
        float d[2][4][4];
#pragma unroll
        for (int i = 0; i < 2; i++)
#pragma unroll
            for (int j = 0; j < 4; j++)
#pragma unroll
                for (int q = 0; q < 4; q++) d[i][j][q] = 0.f;

#pragma unroll
        for (int kk = 0; kk < RNK; kk += 8) {
            unsigned af[2][4], bf[4][2];
#pragma unroll
            for (int mt = 0; mt < 2; mt++) {
                int r0 = warpM * 32 + mt * 16 + g;
                int c = p * RNK + kk + tg;
                af[mt][0] = __float_as_uint(XAs[r0 * XAS_STRIDE + c]);
                af[mt][1] = __float_as_uint(XAs[(r0 + 8) * XAS_STRIDE + c]);
                af[mt][2] = __float_as_uint(XAs[r0 * XAS_STRIDE + c + 4]);
                af[mt][3] = __float_as_uint(XAs[(r0 + 8) * XAS_STRIDE + c + 4]);
            }
#pragma unroll
            for (int nt = 0; nt < 4; nt++) {
                int n = warpN * 32 + nt * 8 + g;
                bf[nt][0] = __float_as_uint(Bep[(p * BN + n) * BEP_STRIDE + kk + tg]);
                bf[nt][1] = __float_as_uint(Bep[(p * BN + n) * BEP_STRIDE + kk + tg + 4]);
            }
#pragma unroll
            for (int mt = 0; mt < 2; mt++)
#pragma unroll
                for (int nt = 0; nt < 4; nt++)
                    mma8(d[mt][nt], af[mt][0], af[mt][1], af[mt][2], af[mt][3],
                         bf[nt][0], bf[nt][1]);
        }

        float* op = out + (size_t)p * M_TOT * N_TOT;
        float s = scl[p];
#pragma unroll
        for (int mt = 0; mt < 2; mt++)
#pragma unroll
            for (int nt = 0; nt < 4; nt++) {
                int row = bm * BM + warpM * 32 + mt * 16 + g;
                int col = bn * BN + warpN * 32 + nt * 8 + tg * 2;
                float2 v0 = make_float2(acc[mt][nt][0] + s * d[mt][nt][0] + bv0[nt],
                                        acc[mt][nt][1] + s * d[mt][nt][1] + bv1[nt]);
                float2 v1 = make_float2(acc[mt][nt][2] + s * d[mt][nt][2] + bv0[nt],
                                        acc[mt][nt][3] + s * d[mt][nt][3] + bv1[nt]);
                __stcs((float2*)&op[(size_t)row * N_TOT + col], v0);
                __stcs((float2*)&op[(size_t)(row + 8) * N_TOT + col], v1);
            }
    }
}

// ---------------------------------------------------------------------------
extern "C" void kernel_launch(void* const* d_in, const int* in_sizes, int n_in,
                              void* d_out, int out_size) {
    const float* x = (const float*)d_in[0];
    const float* W = (const float*)d_in[1];
    const float* b = (const float*)d_in[2];
    const float* A_sh = (const float*)d_in[3];
    const float* B_sh = (const float*)d_in[4];
    const float* A_tasks = (const float*)d_in[5];
    const float* B_tasks = (const float*)d_in[6];
    const float* scales = (const float*)d_in[7];
    float* out = (float*)d_out;

    const int xa_smem = (3 * (X_BM + X_BN) * TSTRIDE) * 4;                   // 89856 B
    const int main_smem =
        (3 * (BM + BN) * TSTRIDE + BM * XAS_STRIDE + NPLANE * BN * BEP_STRIDE) * 4;  // 204800 B

    cudaFuncSetAttribute(xa_kernel, cudaFuncAttributeMaxDynamicSharedMemorySize, xa_smem);
    cudaFuncSetAttribute(main_kernel, cudaFuncAttributeMaxDynamicSharedMemorySize, main_smem);

    round_w_kernel<<<1024, 256>>>(W);
    round_a_kernel<<<320, 256>>>(A_sh, A_tasks);
    xa_kernel<<<M_TOT / X_BM, 256, xa_smem>>>(x);
    main_kernel<<<dim3(N_TOT / BN, M_TOT / BM), NTHR, main_smem>>>(x, b, B_sh, B_tasks,
                                                                   scales, out);
    (void)in_sizes; (void)n_in; (void)out_size;
}

// round 6
// speedup vs baseline: 1.2205x; 1.1691x over previous
#include <cuda_runtime.h>
#include <cstdint>

// Problem dims
#define M_TOT 32768
#define K_TOT 1024
#define N_TOT 1024
#define RNK   16
#define NPLANE 5
#define XA_COLS 80

// ---------------- scratch ----------------
__device__ float g_xa[(size_t)M_TOT * XA_COLS];   // XA = x @ [A_sh; A_tasks]^T
__device__ float g_wr[(size_t)N_TOT * K_TOT];     // W rounded to tf32 (rna)
__device__ float g_ar[(size_t)XA_COLS * K_TOT];   // [A_sh; A_tasks] rounded to tf32

__device__ __forceinline__ unsigned f2tf(float f) {
    unsigned u;
    asm("cvt.rna.tf32.f32 %0, %1;" : "=r"(u) : "f"(f));
    return u;
}
__device__ __forceinline__ uint32_t smem_u32(const void* p) {
    return (uint32_t)__cvta_generic_to_shared(p);
}
#define CP16(d, s) asm volatile("cp.async.cg.shared.global [%0], [%1], 16;" ::"r"(d), "l"(s))
#define CPC() asm volatile("cp.async.commit_group;")
#define CPW(n) asm volatile("cp.async.wait_group %0;" ::"n"(n))

__device__ __forceinline__ void mma8(float c[4], unsigned a0, unsigned a1, unsigned a2,
                                     unsigned a3, unsigned b0, unsigned b1) {
    asm volatile(
        "mma.sync.aligned.m16n8k8.row.col.f32.tf32.tf32.f32 "
        "{%0,%1,%2,%3},{%4,%5,%6,%7},{%8,%9},{%0,%1,%2,%3};"
        : "+f"(c[0]), "+f"(c[1]), "+f"(c[2]), "+f"(c[3])
        : "r"(a0), "r"(a1), "r"(a2), "r"(a3), "r"(b0), "r"(b1));
}

// ---------------------------------------------------------------------------
// Pre-round W and A to tf32 (rna): hot loops then skip cvt entirely
// (HMMA truncates operands; pre-rounded operands behave as round-to-nearest).
// ---------------------------------------------------------------------------
__global__ void round_w_kernel(const float* __restrict__ W) {
    int i = blockIdx.x * 1024 + threadIdx.x;
#pragma unroll
    for (int j = 0; j < 4; j++)
        g_wr[i + j * 256] = __uint_as_float(f2tf(W[i + j * 256]));
}
__global__ void round_a_kernel(const float* __restrict__ A_sh,
                               const float* __restrict__ A_tasks) {
    int i = blockIdx.x * 256 + threadIdx.x;
    float v = (i < RNK * K_TOT) ? A_sh[i] : A_tasks[i - RNK * K_TOT];
    g_ar[i] = __uint_as_float(f2tf(v));
}

// ---------------------------------------------------------------------------
// Kernel 1: XA = x @ [A_sh; A_tasks]^T   (unchanged from R4; passed)
// ---------------------------------------------------------------------------
#define BKX 32
#define TST 36
#define X_BM 128
#define X_BN 80

__global__ void __launch_bounds__(256, 2) xa_kernel(const float* __restrict__ x) {
    extern __shared__ float sm[];
    float* As = sm;
    float* Bs = sm + 3 * X_BM * TST;

    const int tid = threadIdx.x;
    const int lane = tid & 31, wid = tid >> 5;
    const int warpM = wid >> 1, warpN = wid & 1;
    const int bm = blockIdx.x;
    const int g = lane >> 2, tg = lane & 3;

    float acc[2][5][4];
#pragma unroll
    for (int i = 0; i < 2; i++)
#pragma unroll
        for (int j = 0; j < 5; j++)
#pragma unroll
            for (int q = 0; q < 4; q++) acc[i][j][q] = 0.f;

    auto load_stage = [&](int buf, int kt) {
        const float* asrc = x + (size_t)(bm * X_BM) * K_TOT + kt * BKX;
        float* ad = As + buf * X_BM * TST;
#pragma unroll
        for (int i = 0; i < 4; i++) {
            int idx = tid + i * 256;
            int r = idx >> 3, v = idx & 7;
            CP16(smem_u32(ad + r * TST + v * 4), asrc + (size_t)r * K_TOT + v * 4);
        }
        float* bd = Bs + buf * X_BN * TST;
        for (int idx = tid; idx < X_BN * 8; idx += 256) {
            int r = idx >> 3, v = idx & 7;
            CP16(smem_u32(bd + r * TST + v * 4),
                 g_ar + (size_t)r * K_TOT + kt * BKX + v * 4);
        }
    };

    load_stage(0, 0); CPC();
    load_stage(1, 1); CPC();

    const int KT = K_TOT / BKX;
    for (int kt = 0; kt < KT; kt++) {
        CPW(1);
        __syncthreads();
        if (kt + 2 < KT) load_stage((kt + 2) % 3, kt + 2);
        CPC();
        const float* A = As + (kt % 3) * X_BM * TST;
        const float* B = Bs + (kt % 3) * X_BN * TST;
#pragma unroll
        for (int kk = 0; kk < BKX; kk += 8) {
            unsigned af[2][4], bf[5][2];
#pragma unroll
            for (int mt = 0; mt < 2; mt++) {
                int r0 = warpM * 32 + mt * 16 + g;
                af[mt][0] = __float_as_uint(A[r0 * TST + kk + tg]);
                af[mt][1] = __float_as_uint(A[(r0 + 8) * TST + kk + tg]);
                af[mt][2] = __float_as_uint(A[r0 * TST + kk + tg + 4]);
                af[mt][3] = __float_as_uint(A[(r0 + 8) * TST + kk + tg + 4]);
            }
#pragma unroll
            for (int nt = 0; nt < 5; nt++) {
                int n = warpN * 40 + nt * 8 + g;
                bf[nt][0] = __float_as_uint(B[n * TST + kk + tg]);
                bf[nt][1] = __float_as_uint(B[n * TST + kk + tg + 4]);
            }
#pragma unroll
            for (int mt = 0; mt < 2; mt++)
#pragma unroll
                for (int nt = 0; nt < 5; nt++)
                    mma8(acc[mt][nt], af[mt][0], af[mt][1], af[mt][2], af[mt][3],
                         bf[nt][0], bf[nt][1]);
        }
    }

#pragma unroll
    for (int mt = 0; mt < 2; mt++)
#pragma unroll
        for (int nt = 0; nt < 5; nt++) {
            int row = bm * X_BM + warpM * 32 + mt * 16 + g;
            int col = warpN * 40 + nt * 8 + tg * 2;
            *(float2*)&g_xa[(size_t)row * XA_COLS + col] =
                make_float2(acc[mt][nt][0], acc[mt][nt][1]);
            *(float2*)&g_xa[(size_t)(row + 8) * XA_COLS + col] =
                make_float2(acc[mt][nt][2], acc[mt][nt][3]);
        }
}

// ---------------------------------------------------------------------------
// Kernel 2: main fused GEMM. CTA 256x128, 8 warps (4x2) of 64x64 tiles.
// Permuted-K vectorized fragment loads (LDS.128). Epilogue tiles reuse
// retired pipeline stages. BK=32, 3-stage cp.async pipeline.
// ---------------------------------------------------------------------------
#define BM 256
#define BN 128
#define BK 32
#define STG_F ((BM + BN) * TST)   // 13824 floats / stage (55296 B)
#define SMEM_MAIN (3 * STG_F * 4) // 165888 B
#define XAS_OFF STG_F             // XA tile at stages 1..2 region
#define XAS_ST 84
#define BEP_ST 20

__global__ void __launch_bounds__(256, 1) main_kernel(
    const float* __restrict__ x, const float* __restrict__ bias,
    const float* __restrict__ B_sh, const float* __restrict__ B_tasks,
    const float* __restrict__ scales, float* __restrict__ out) {
    extern __shared__ float sm[];
    const int tid = threadIdx.x;
    const int lane = tid & 31, wid = tid >> 5;
    const int warpM = wid >> 1, warpN = wid & 1;   // 4 x 2 of 64x64
    const int bn = blockIdx.x, bm = blockIdx.y;
    const int g = lane >> 2, tg = lane & 3;

    float acc[4][8][4];
#pragma unroll
    for (int i = 0; i < 4; i++)
#pragma unroll
        for (int j = 0; j < 8; j++)
#pragma unroll
            for (int q = 0; q < 4; q++) acc[i][j][q] = 0.f;

    auto ld_stage = [&](int buf, int kt) {
        const float* ax = x + (size_t)(bm * BM) * K_TOT + kt * BK;
        const float* bw = g_wr + (size_t)(bn * BN) * K_TOT + kt * BK;
        float* ad = sm + buf * STG_F;
        float* bd = ad + BM * TST;
#pragma unroll
        for (int i = 0; i < 8; i++) {
            int idx = tid + i * 256;
            int r = idx >> 3, v = idx & 7;
            CP16(smem_u32(ad + r * TST + v * 4), ax + (size_t)r * K_TOT + v * 4);
        }
#pragma unroll
        for (int i = 0; i < 4; i++) {
            int idx = tid + i * 256;
            int r = idx >> 3, v = idx & 7;
            CP16(smem_u32(bd + r * TST + v * 4), bw + (size_t)r * K_TOT + v * 4);
        }
    };

    // stage schedule: k-tile kt lives in buf (kt+2)%3  -> last kt=31 uses buf 0,
    // so stages 1,2 (contiguous region) are free at top of kt=31 for the XA tile.
    ld_stage(2, 0); CPC();
    ld_stage(0, 1); CPC();

    const int KT = K_TOT / BK;  // 32
    for (int kt = 0; kt < KT; kt++) {
        CPW(1);
        __syncthreads();
        if (kt == KT - 1) {
            // XA epilogue tile into stages 1..2 region (both retired now)
            float* xd = sm + XAS_OFF;
            const float* xs = g_xa + (size_t)(bm * BM) * XA_COLS;
            for (int idx = tid; idx < BM * 20; idx += 256) {
                int r = idx / 20, v = idx % 20;
                CP16(smem_u32(xd + r * XAS_ST + v * 4), xs + (size_t)r * XA_COLS + v * 4);
            }
        }
        if (kt + 2 < KT) ld_stage((kt + 1) % 3, kt + 2);
        CPC();

        const float* A = sm + ((kt + 2) % 3) * STG_F;
        const float* B = A + BM * TST;

        // Permuted-K fragments: thread tg covers physical k in [8tg, 8tg+8);
        // k-step j uses slots (2j, 2j+1). Same map on A and B -> correct dot.
        float4 vbq[8][2];
#pragma unroll
        for (int nt = 0; nt < 8; nt++) {
            int n = warpN * 64 + nt * 8 + g;
            vbq[nt][0] = *(const float4*)&B[n * TST + 8 * tg];
            vbq[nt][1] = *(const float4*)&B[n * TST + 8 * tg + 4];
        }
        const float* vb = (const float*)vbq;
#pragma unroll
        for (int mt = 0; mt < 4; mt++) {
            int r0 = warpM * 64 + mt * 16 + g;
            float4 vaq[2][2];
            vaq[0][0] = *(const float4*)&A[r0 * TST + 8 * tg];
            vaq[0][1] = *(const float4*)&A[r0 * TST + 8 * tg + 4];
            vaq[1][0] = *(const float4*)&A[(r0 + 8) * TST + 8 * tg];
            vaq[1][1] = *(const float4*)&A[(r0 + 8) * TST + 8 * tg + 4];
            const float* va = (const float*)vaq;
#pragma unroll
            for (int j = 0; j < 4; j++) {
                unsigned a0 = __float_as_uint(va[2 * j]);
                unsigned a1 = __float_as_uint(va[8 + 2 * j]);
                unsigned a2 = __float_as_uint(va[2 * j + 1]);
                unsigned a3 = __float_as_uint(va[8 + 2 * j + 1]);
#pragma unroll
                for (int nt = 0; nt < 8; nt++)
                    mma8(acc[mt][nt], a0, a1, a2, a3,
                         __float_as_uint(vb[nt * 8 + 2 * j]),
                         __float_as_uint(vb[nt * 8 + 2 * j + 1]));
            }
        }
    }

    // Bep tile into retired stage 0
    __syncthreads();
    for (int idx = tid; idx < NPLANE * BN * 4; idx += 256) {
        int p = idx >> 9, rem = idx & 511;
        int n = rem >> 2, v = rem & 3;
        const float* src =
            (p == 0) ? (B_sh + (size_t)(bn * BN + n) * RNK + v * 4)
                     : (B_tasks + ((size_t)(p - 1) * N_TOT + bn * BN + n) * RNK + v * 4);
        CP16(smem_u32(sm + (p * BN + n) * BEP_ST + v * 4), src);
    }
    CPC();
    CPW(0);
    __syncthreads();

    // ---- Epilogue ----
    float scl[NPLANE];
    scl[0] = 1.f;
#pragma unroll
    for (int p = 1; p < NPLANE; p++) scl[p] = __ldg(&scales[p - 1]);

    // fold bias into acc
#pragma unroll
    for (int nt = 0; nt < 8; nt++) {
        int c = bn * BN + warpN * 64 + nt * 8 + tg * 2;
        float b0 = __ldg(&bias[c]), b1 = __ldg(&bias[c + 1]);
#pragma unroll
        for (int mt = 0; mt < 4; mt++) {
            acc[mt][nt][0] += b0; acc[mt][nt][1] += b1;
            acc[mt][nt][2] += b0; acc[mt][nt][3] += b1;
        }
    }

    const float* XAs = sm + XAS_OFF;
    const float* Bep = sm;

#pragma unroll
    for (int p = 0; p < NPLANE; p++) {
        float s = scl[p];
        float* op = out + (size_t)p * M_TOT * N_TOT;
#pragma unroll
        for (int h = 0; h < 2; h++) {   // n-halves to bound register pressure
            float d[4][4][4];
#pragma unroll
            for (int i = 0; i < 4; i++)
#pragma unroll
                for (int j = 0; j < 4; j++)
#pragma unroll
                    for (int q = 0; q < 4; q++) d[i][j][q] = 0.f;

#pragma unroll
            for (int kk = 0; kk < RNK; kk += 8) {
                unsigned af[4][4], bf[4][2];
#pragma unroll
                for (int mt = 0; mt < 4; mt++) {
                    int r0 = warpM * 64 + mt * 16 + g;
                    int c = p * RNK + kk + tg;
                    af[mt][0] = __float_as_uint(XAs[r0 * XAS_ST + c]);
                    af[mt][1] = __float_as_uint(XAs[(r0 + 8) * XAS_ST + c]);
                    af[mt][2] = __float_as_uint(XAs[r0 * XAS_ST + c + 4]);
                    af[mt][3] = __float_as_uint(XAs[(r0 + 8) * XAS_ST + c + 4]);
                }
#pragma unroll
                for (int nt = 0; nt < 4; nt++) {
                    int n = warpN * 64 + h * 32 + nt * 8 + g;
                    bf[nt][0] = __float_as_uint(Bep[(p * BN + n) * BEP_ST + kk + tg]);
                    bf[nt][1] = __float_as_uint(Bep[(p * BN + n) * BEP_ST + kk + tg + 4]);
                }
#pragma unroll
                for (int mt = 0; mt < 4; mt++)
#pragma unroll
                    for (int nt = 0; nt < 4; nt++)
                        mma8(d[mt][nt], af[mt][0], af[mt][1], af[mt][2], af[mt][3],
                             bf[nt][0], bf[nt][1]);
            }

#pragma unroll
            for (int mt = 0; mt < 4; mt++)
#pragma unroll
                for (int nt = 0; nt < 4; nt++) {
                    int ntg = h * 4 + nt;
                    int row = bm * BM + warpM * 64 + mt * 16 + g;
                    int col = bn * BN + warpN * 64 + h * 32 + nt * 8 + tg * 2;
                    float2 v0 = make_float2(acc[mt][ntg][0] + s * d[mt][nt][0],
                                            acc[mt][ntg][1] + s * d[mt][nt][1]);
                    float2 v1 = make_float2(acc[mt][ntg][2] + s * d[mt][nt][2],
                                            acc[mt][ntg][3] + s * d[mt][nt][3]);
                    __stcs((float2*)&op[(size_t)row * N_TOT + col], v0);
                    __stcs((float2*)&op[(size_t)(row + 8) * N_TOT + col], v1);
                }
        }
    }
}

// ---------------------------------------------------------------------------
extern "C" void kernel_launch(void* const* d_in, const int* in_sizes, int n_in,
                              void* d_out, int out_size) {
    const float* x = (const float*)d_in[0];
    const float* W = (const float*)d_in[1];
    const float* b = (const float*)d_in[2];
    const float* A_sh = (const float*)d_in[3];
    const float* B_sh = (const float*)d_in[4];
    const float* A_tasks = (const float*)d_in[5];
    const float* B_tasks = (const float*)d_in[6];
    const float* scales = (const float*)d_in[7];
    float* out = (float*)d_out;

    const int xa_smem = (3 * (X_BM + X_BN) * TST) * 4;   // 89856 B

    cudaFuncSetAttribute(xa_kernel, cudaFuncAttributeMaxDynamicSharedMemorySize, xa_smem);
    cudaFuncSetAttribute(main_kernel, cudaFuncAttributeMaxDynamicSharedMemorySize, SMEM_MAIN);

    round_w_kernel<<<1024, 256>>>(W);
    round_a_kernel<<<320, 256>>>(A_sh, A_tasks);
    xa_kernel<<<M_TOT / X_BM, 256, xa_smem>>>(x);
    main_kernel<<<dim3(N_TOT / BN, M_TOT / BM), 256, SMEM_MAIN>>>(x, b, B_sh, B_tasks,
                                                                  scales, out);
    (void)in_sizes; (void)n_in; (void)out_size;
}

// round 8
// speedup vs baseline: 1.7886x; 1.4654x over previous
#include <cuda_runtime.h>
#include <cuda_fp16.h>
#include <cstdint>

// Problem dims
#define M_TOT 32768
#define K_TOT 1024
#define N_TOT 1024
#define RNK   16
#define NPLANE 5
#define XA_COLS 80

// ---------------- scratch ----------------
__device__ __half g_xh[(size_t)M_TOT * K_TOT];      // x in fp16
__device__ __half g_wh[(size_t)N_TOT * K_TOT];      // W in fp16
__device__ __half g_bh[(size_t)NPLANE * N_TOT * RNK]; // [B_sh; B_tasks] fp16
__device__ float  g_ar[(size_t)XA_COLS * K_TOT];    // A matrices tf32-rounded
__device__ __half g_xah[(size_t)M_TOT * XA_COLS];   // XA result in fp16

__device__ __forceinline__ unsigned f2tf(float f) {
    unsigned u;
    asm("cvt.rna.tf32.f32 %0, %1;" : "=r"(u) : "f"(f));
    return u;
}
__device__ __forceinline__ uint32_t smem_u32(const void* p) {
    return (uint32_t)__cvta_generic_to_shared(p);
}
#define CP16(d, s) asm volatile("cp.async.cg.shared.global [%0], [%1], 16;" ::"r"(d), "l"(s))
#define CPC() asm volatile("cp.async.commit_group;")
#define CPW(n) asm volatile("cp.async.wait_group %0;" ::"n"(n))

// tf32 mma (xa kernel only)
__device__ __forceinline__ void mma8(float c[4], unsigned a0, unsigned a1, unsigned a2,
                                     unsigned a3, unsigned b0, unsigned b1) {
    asm volatile(
        "mma.sync.aligned.m16n8k8.row.col.f32.tf32.tf32.f32 "
        "{%0,%1,%2,%3},{%4,%5,%6,%7},{%8,%9},{%0,%1,%2,%3};"
        : "+f"(c[0]), "+f"(c[1]), "+f"(c[2]), "+f"(c[3])
        : "r"(a0), "r"(a1), "r"(a2), "r"(a3), "r"(b0), "r"(b1));
}
// fp16 mma, fp32 accum
__device__ __forceinline__ void mma16(float c[4], unsigned a0, unsigned a1, unsigned a2,
                                      unsigned a3, unsigned b0, unsigned b1) {
    asm volatile(
        "mma.sync.aligned.m16n8k16.row.col.f32.f16.f16.f32 "
        "{%0,%1,%2,%3},{%4,%5,%6,%7},{%8,%9},{%0,%1,%2,%3};"
        : "+f"(c[0]), "+f"(c[1]), "+f"(c[2]), "+f"(c[3])
        : "r"(a0), "r"(a1), "r"(a2), "r"(a3), "r"(b0), "r"(b1));
}

// ---------------------------------------------------------------------------
// Pre-convert kernels
// ---------------------------------------------------------------------------
__global__ void cvt_x_kernel(const float* __restrict__ x) {
    size_t i = ((size_t)blockIdx.x * 256 + threadIdx.x) * 8;
    float4 v0 = *(const float4*)(x + i);
    float4 v1 = *(const float4*)(x + i + 4);
    __half2 h0 = __floats2half2_rn(v0.x, v0.y), h1 = __floats2half2_rn(v0.z, v0.w);
    __half2 h2 = __floats2half2_rn(v1.x, v1.y), h3 = __floats2half2_rn(v1.z, v1.w);
    uint4 o;
    o.x = *(uint32_t*)&h0; o.y = *(uint32_t*)&h1;
    o.z = *(uint32_t*)&h2; o.w = *(uint32_t*)&h3;
    *(uint4*)(g_xh + i) = o;
}
__global__ void cvt_w_kernel(const float* __restrict__ W) {
    size_t i = ((size_t)blockIdx.x * 256 + threadIdx.x) * 8;
    float4 v0 = *(const float4*)(W + i);
    float4 v1 = *(const float4*)(W + i + 4);
    __half2 h0 = __floats2half2_rn(v0.x, v0.y), h1 = __floats2half2_rn(v0.z, v0.w);
    __half2 h2 = __floats2half2_rn(v1.x, v1.y), h3 = __floats2half2_rn(v1.z, v1.w);
    uint4 o;
    o.x = *(uint32_t*)&h0; o.y = *(uint32_t*)&h1;
    o.z = *(uint32_t*)&h2; o.w = *(uint32_t*)&h3;
    *(uint4*)(g_wh + i) = o;
}
__global__ void cvt_b_kernel(const float* __restrict__ B_sh,
                             const float* __restrict__ B_tasks) {
    int i = blockIdx.x * 256 + threadIdx.x;   // 320 blocks -> 81920
    float v = (i < N_TOT * RNK) ? B_sh[i] : B_tasks[i - N_TOT * RNK];
    g_bh[i] = __float2half_rn(v);
}
__global__ void round_a_kernel(const float* __restrict__ A_sh,
                               const float* __restrict__ A_tasks) {
    int i = blockIdx.x * 256 + threadIdx.x;
    float v = (i < RNK * K_TOT) ? A_sh[i] : A_tasks[i - RNK * K_TOT];
    g_ar[i] = __uint_as_float(f2tf(v));
}

// ---------------------------------------------------------------------------
// Kernel 1: XA = x @ [A_sh; A_tasks]^T  (tf32; proven). Output stored fp16.
// ---------------------------------------------------------------------------
#define BKX 32
#define TST 36
#define X_BM 128
#define X_BN 80

__global__ void __launch_bounds__(256, 2) xa_kernel(const float* __restrict__ x) {
    extern __shared__ float sm[];
    float* As = sm;
    float* Bs = sm + 3 * X_BM * TST;

    const int tid = threadIdx.x;
    const int lane = tid & 31, wid = tid >> 5;
    const int warpM = wid >> 1, warpN = wid & 1;
    const int bm = blockIdx.x;
    const int g = lane >> 2, tg = lane & 3;

    float acc[2][5][4];
#pragma unroll
    for (int i = 0; i < 2; i++)
#pragma unroll
        for (int j = 0; j < 5; j++)
#pragma unroll
            for (int q = 0; q < 4; q++) acc[i][j][q] = 0.f;

    auto load_stage = [&](int buf, int kt) {
        const float* asrc = x + (size_t)(bm * X_BM) * K_TOT + kt * BKX;
        float* ad = As + buf * X_BM * TST;
#pragma unroll
        for (int i = 0; i < 4; i++) {
            int idx = tid + i * 256;
            int r = idx >> 3, v = idx & 7;
            CP16(smem_u32(ad + r * TST + v * 4), asrc + (size_t)r * K_TOT + v * 4);
        }
        float* bd = Bs + buf * X_BN * TST;
        for (int idx = tid; idx < X_BN * 8; idx += 256) {
            int r = idx >> 3, v = idx & 7;
            CP16(smem_u32(bd + r * TST + v * 4),
                 g_ar + (size_t)r * K_TOT + kt * BKX + v * 4);
        }
    };

    load_stage(0, 0); CPC();
    load_stage(1, 1); CPC();

    const int KT = K_TOT / BKX;
    for (int kt = 0; kt < KT; kt++) {
        CPW(1);
        __syncthreads();
        if (kt + 2 < KT) load_stage((kt + 2) % 3, kt + 2);
        CPC();
        const float* A = As + (kt % 3) * X_BM * TST;
        const float* B = Bs + (kt % 3) * X_BN * TST;
#pragma unroll
        for (int kk = 0; kk < BKX; kk += 8) {
            unsigned af[2][4], bf[5][2];
#pragma unroll
            for (int mt = 0; mt < 2; mt++) {
                int r0 = warpM * 32 + mt * 16 + g;
                af[mt][0] = __float_as_uint(A[r0 * TST + kk + tg]);
                af[mt][1] = __float_as_uint(A[(r0 + 8) * TST + kk + tg]);
                af[mt][2] = __float_as_uint(A[r0 * TST + kk + tg + 4]);
                af[mt][3] = __float_as_uint(A[(r0 + 8) * TST + kk + tg + 4]);
            }
#pragma unroll
            for (int nt = 0; nt < 5; nt++) {
                int n = warpN * 40 + nt * 8 + g;
                bf[nt][0] = __float_as_uint(B[n * TST + kk + tg]);
                bf[nt][1] = __float_as_uint(B[n * TST + kk + tg + 4]);
            }
#pragma unroll
            for (int mt = 0; mt < 2; mt++)
#pragma unroll
                for (int nt = 0; nt < 5; nt++)
                    mma8(acc[mt][nt], af[mt][0], af[mt][1], af[mt][2], af[mt][3],
                         bf[nt][0], bf[nt][1]);
        }
    }

#pragma unroll
    for (int mt = 0; mt < 2; mt++)
#pragma unroll
        for (int nt = 0; nt < 5; nt++) {
            int row = bm * X_BM + warpM * 32 + mt * 16 + g;
            int col = warpN * 40 + nt * 8 + tg * 2;
            *(__half2*)&g_xah[(size_t)row * XA_COLS + col] =
                __floats2half2_rn(acc[mt][nt][0], acc[mt][nt][1]);
            *(__half2*)&g_xah[(size_t)(row + 8) * XA_COLS + col] =
                __floats2half2_rn(acc[mt][nt][2], acc[mt][nt][3]);
        }
}

// ---------------------------------------------------------------------------
// Kernel 2: main fused GEMM, fp16 m16n8k16. CTA 256x128, 8 warps (4x2) of
// 64x64. 4-stage pipeline, XOR-swizzled 64B rows, permuted-K LDS.128.
// ---------------------------------------------------------------------------
#define BM 256
#define BN 128
#define STG_B 24576                 // (256+128) rows * 64 B
#define NST 4
#define OFF_XA (NST * STG_B)        // 98304 ; XA tile 256*160B = 40960
#define OFF_BEP (OFF_XA + 256 * 160)        // 139264 ; Bep 5*128*32 = 20480
#define SMEM_MAIN (OFF_BEP + NPLANE * 128 * 32)  // 159744

__global__ void __launch_bounds__(256, 1) main_kernel(
    const float* __restrict__ bias, const float* __restrict__ scales,
    float* __restrict__ out) {
    extern __shared__ char smc[];
    const int tid = threadIdx.x;
    const int lane = tid & 31, wid = tid >> 5;
    const int warpM = wid >> 1, warpN = wid & 1;   // 4 x 2 of 64x64
    const int bn = blockIdx.x, bm = blockIdx.y;
    const int g = lane >> 2, tg = lane & 3;

    float acc[4][8][4];
#pragma unroll
    for (int i = 0; i < 4; i++)
#pragma unroll
        for (int j = 0; j < 8; j++)
#pragma unroll
            for (int q = 0; q < 4; q++) acc[i][j][q] = 0.f;

    // ---- epilogue tiles: first commit group ----
    {   // XA tile: 256 rows x 160B (80 halves)
        const __half* xs = g_xah + (size_t)(bm * BM) * XA_COLS;
#pragma unroll
        for (int i = 0; i < 10; i++) {
            int idx = tid + i * 256;
            int r = idx / 10, c = idx % 10;
            CP16(smem_u32(smc + OFF_XA + r * 160 + c * 16), xs + (size_t)r * XA_COLS + c * 8);
        }
        // Bep: 5*128 rows x 32B
#pragma unroll
        for (int i = 0; i < 5; i++) {
            int idx = tid + i * 256;                // 1280 chunks
            int p = idx >> 8, n = (idx >> 1) & 127, c = idx & 1;
            CP16(smem_u32(smc + OFF_BEP + (p * 128 + n) * 32 + c * 16),
                 g_bh + ((size_t)p * N_TOT + bn * BN + n) * RNK + c * 8);
        }
    }

    auto ld_stage = [&](int buf, int kt) {
        const __half* ax = g_xh + (size_t)(bm * BM) * K_TOT + kt * 32;
        const __half* bw = g_wh + (size_t)(bn * BN) * K_TOT + kt * 32;
        char* ad = smc + buf * STG_B;
        char* bd = ad + BM * 64;
#pragma unroll
        for (int i = 0; i < 4; i++) {
            int idx = tid + i * 256;
            int r = idx >> 2, c = idx & 3;
            CP16(smem_u32(ad + r * 64 + ((c ^ (r & 3)) << 4)), ax + (size_t)r * K_TOT + c * 8);
        }
#pragma unroll
        for (int i = 0; i < 2; i++) {
            int idx = tid + i * 256;
            int r = idx >> 2, c = idx & 3;
            CP16(smem_u32(bd + r * 64 + ((c ^ (r & 3)) << 4)), bw + (size_t)r * K_TOT + c * 8);
        }
    };

    ld_stage(0, 0); CPC();    // group 0 = epi tiles + stage 0
    ld_stage(1, 1); CPC();
    ld_stage(2, 2); CPC();

    const int KT = K_TOT / 32;  // 32
    for (int kt = 0; kt < KT; kt++) {
        CPW(2);
        __syncthreads();
        if (kt + 3 < KT) ld_stage((kt + 3) & 3, kt + 3);
        CPC();

        const char* A = smc + (kt & 3) * STG_B;
        const char* B = A + BM * 64;

        uint4 bq[8];
#pragma unroll
        for (int nt = 0; nt < 8; nt++) {
            int n = warpN * 64 + nt * 8 + g;
            bq[nt] = *(const uint4*)(B + n * 64 + ((tg ^ (n & 3)) << 4));
        }
#pragma unroll
        for (int mt = 0; mt < 4; mt++) {
            int r0 = warpM * 64 + mt * 16 + g;
            int sw = (tg ^ (r0 & 3)) << 4;
            uint4 a0 = *(const uint4*)(A + r0 * 64 + sw);
            uint4 a1 = *(const uint4*)(A + (r0 + 8) * 64 + sw);
#pragma unroll
            for (int nt = 0; nt < 8; nt++)
                mma16(acc[mt][nt], a0.x, a1.x, a0.y, a1.y, bq[nt].x, bq[nt].y);
#pragma unroll
            for (int nt = 0; nt < 8; nt++)
                mma16(acc[mt][nt], a0.z, a1.z, a0.w, a1.w, bq[nt].z, bq[nt].w);
        }
    }

    CPW(0);
    __syncthreads();

    // ---- Epilogue ----
    float scl[NPLANE];
    scl[0] = 1.f;
#pragma unroll
    for (int p = 1; p < NPLANE; p++) scl[p] = __ldg(&scales[p - 1]);

#pragma unroll
    for (int nt = 0; nt < 8; nt++) {
        int c = bn * BN + warpN * 64 + nt * 8 + tg * 2;
        float b0 = __ldg(&bias[c]), b1 = __ldg(&bias[c + 1]);
#pragma unroll
        for (int mt = 0; mt < 4; mt++) {
            acc[mt][nt][0] += b0; acc[mt][nt][1] += b1;
            acc[mt][nt][2] += b0; acc[mt][nt][3] += b1;
        }
    }

    const char* XAs = smc + OFF_XA;
    const char* Bep = smc + OFF_BEP;
    const int sH = tg >> 1, sL = tg & 1;   // permuted k16: thread covers 8*sL+4*sH+[0,4)

#pragma unroll
    for (int p = 0; p < NPLANE; p++) {
        float s = scl[p];
        float* op = out + (size_t)p * M_TOT * N_TOT;

        unsigned bb[8][2];
#pragma unroll
        for (int nt = 0; nt < 8; nt++) {
            int n = warpN * 64 + nt * 8 + g;
            uint4 v = *(const uint4*)(Bep + (p * 128 + n) * 32 + sL * 16);
            bb[nt][0] = sH ? v.z : v.x;
            bb[nt][1] = sH ? v.w : v.y;
        }

#pragma unroll
        for (int mt = 0; mt < 4; mt++) {
            int r0 = warpM * 64 + mt * 16 + g;
            uint4 x0 = *(const uint4*)(XAs + r0 * 160 + p * 32 + sL * 16);
            uint4 x1 = *(const uint4*)(XAs + (r0 + 8) * 160 + p * 32 + sL * 16);
            unsigned a0 = sH ? x0.z : x0.x, a2 = sH ? x0.w : x0.y;
            unsigned a1 = sH ? x1.z : x1.x, a3 = sH ? x1.w : x1.y;

            float d[8][4];
#pragma unroll
            for (int nt = 0; nt < 8; nt++) {
#pragma unroll
                for (int q = 0; q < 4; q++) d[nt][q] = 0.f;
                mma16(d[nt], a0, a1, a2, a3, bb[nt][0], bb[nt][1]);
            }

            int row = bm * BM + r0;
#pragma unroll
            for (int nt = 0; nt < 8; nt++) {
                int col = bn * BN + warpN * 64 + nt * 8 + tg * 2;
                float2 v0 = make_float2(acc[mt][nt][0] + s * d[nt][0],
                                        acc[mt][nt][1] + s * d[nt][1]);
                float2 v1 = make_float2(acc[mt][nt][2] + s * d[nt][2],
                                        acc[mt][nt][3] + s * d[nt][3]);
                __stcs((float2*)&op[(size_t)row * N_TOT + col], v0);
                __stcs((float2*)&op[(size_t)(row + 8) * N_TOT + col], v1);
            }
        }
    }
}

// ---------------------------------------------------------------------------
extern "C" void kernel_launch(void* const* d_in, const int* in_sizes, int n_in,
                              void* d_out, int out_size) {
    const float* x = (const float*)d_in[0];
    const float* W = (const float*)d_in[1];
    const float* b = (const float*)d_in[2];
    const float* A_sh = (const float*)d_in[3];
    const float* B_sh = (const float*)d_in[4];
    const float* A_tasks = (const float*)d_in[5];
    const float* B_tasks = (const float*)d_in[6];
    const float* scales = (const float*)d_in[7];
    float* out = (float*)d_out;

    const int xa_smem = (3 * (X_BM + X_BN) * TST) * 4;   // 89856 B

    cudaFuncSetAttribute(xa_kernel, cudaFuncAttributeMaxDynamicSharedMemorySize, xa_smem);
    cudaFuncSetAttribute(main_kernel, cudaFuncAttributeMaxDynamicSharedMemorySize, SMEM_MAIN);

    cvt_x_kernel<<<(M_TOT * (K_TOT / 8)) / 256, 256>>>(x);     // 16384 blocks
    cvt_w_kernel<<<(N_TOT * (K_TOT / 8)) / 256, 256>>>(W);     // 512 blocks
    cvt_b_kernel<<<(NPLANE * N_TOT * RNK) / 256, 256>>>(B_sh, B_tasks);
    round_a_kernel<<<(XA_COLS * K_TOT) / 256, 256>>>(A_sh, A_tasks);
    xa_kernel<<<M_TOT / X_BM, 256, xa_smem>>>(x);
    main_kernel<<<dim3(N_TOT / BN, M_TOT / BM), 256, SMEM_MAIN>>>(b, scales, out);
    (void)in_sizes; (void)n_in; (void)out_size;
}

// round 9
// speedup vs baseline: 1.8851x; 1.0540x over previous
#include <cuda_runtime.h>
#include <cuda_fp16.h>
#include <cstdint>

// Problem dims
#define M_TOT 32768
#define K_TOT 1024
#define N_TOT 1024
#define RNK   16
#define NPLANE 5
#define XA_COLS 80

// ---------------- scratch ----------------
__device__ __half g_xh[(size_t)M_TOT * K_TOT];        // x in fp16
__device__ __half g_wh[(size_t)N_TOT * K_TOT];        // W in fp16
__device__ __half g_ah[(size_t)XA_COLS * K_TOT];      // [A_sh; A_tasks] fp16
__device__ __half g_bh[(size_t)NPLANE * N_TOT * RNK]; // [B_sh; B_tasks] fp16
__device__ __half g_xah[(size_t)M_TOT * XA_COLS];     // XA result fp16

__device__ __forceinline__ uint32_t smem_u32(const void* p) {
    return (uint32_t)__cvta_generic_to_shared(p);
}
#define CP16(d, s) asm volatile("cp.async.cg.shared.global [%0], [%1], 16;" ::"r"(d), "l"(s))
#define CPC() asm volatile("cp.async.commit_group;")
#define CPW(n) asm volatile("cp.async.wait_group %0;" ::"n"(n))

// fp16 mma, fp32 accum
__device__ __forceinline__ void mma16(float c[4], unsigned a0, unsigned a1, unsigned a2,
                                      unsigned a3, unsigned b0, unsigned b1) {
    asm volatile(
        "mma.sync.aligned.m16n8k16.row.col.f32.f16.f16.f32 "
        "{%0,%1,%2,%3},{%4,%5,%6,%7},{%8,%9},{%0,%1,%2,%3};"
        : "+f"(c[0]), "+f"(c[1]), "+f"(c[2]), "+f"(c[3])
        : "r"(a0), "r"(a1), "r"(a2), "r"(a3), "r"(b0), "r"(b1));
}

// ---------------------------------------------------------------------------
// Pre-convert kernels (f32 -> fp16 rn)
// ---------------------------------------------------------------------------
__device__ __forceinline__ void cvt8(const float* s, __half* d) {
    float4 v0 = *(const float4*)s;
    float4 v1 = *(const float4*)(s + 4);
    __half2 h0 = __floats2half2_rn(v0.x, v0.y), h1 = __floats2half2_rn(v0.z, v0.w);
    __half2 h2 = __floats2half2_rn(v1.x, v1.y), h3 = __floats2half2_rn(v1.z, v1.w);
    uint4 o;
    o.x = *(uint32_t*)&h0; o.y = *(uint32_t*)&h1;
    o.z = *(uint32_t*)&h2; o.w = *(uint32_t*)&h3;
    *(uint4*)d = o;
}
__global__ void cvt_x_kernel(const float* __restrict__ x) {
    size_t i = ((size_t)blockIdx.x * 256 + threadIdx.x) * 8;
    cvt8(x + i, g_xh + i);
}
__global__ void cvt_w_kernel(const float* __restrict__ W) {
    size_t i = ((size_t)blockIdx.x * 256 + threadIdx.x) * 8;
    cvt8(W + i, g_wh + i);
}
__global__ void cvt_a_kernel(const float* __restrict__ A_sh,
                             const float* __restrict__ A_tasks) {
    int i = blockIdx.x * 256 + threadIdx.x;   // 320 blocks
    float v = (i < RNK * K_TOT) ? A_sh[i] : A_tasks[i - RNK * K_TOT];
    g_ah[i] = __float2half_rn(v);
}
__global__ void cvt_b_kernel(const float* __restrict__ B_sh,
                             const float* __restrict__ B_tasks) {
    int i = blockIdx.x * 256 + threadIdx.x;   // 320 blocks
    float v = (i < N_TOT * RNK) ? B_sh[i] : B_tasks[i - N_TOT * RNK];
    g_bh[i] = __float2half_rn(v);
}

// ---------------------------------------------------------------------------
// Kernel 1: XA = x @ [A_sh; A_tasks]^T   fp16 m16n8k16. CTA 128 rows.
// 8 warps as 4x2 (warp 32x40). 4-stage pipeline, 64B swizzled rows, occ 2.
// ---------------------------------------------------------------------------
#define X_STG 13312   // (128 + 80) rows * 64 B
#define X_SMEM (4 * X_STG)

__global__ void __launch_bounds__(256, 2) xa_kernel() {
    extern __shared__ char smc[];
    const int tid = threadIdx.x;
    const int lane = tid & 31, wid = tid >> 5;
    const int warpM = wid >> 1, warpN = wid & 1;
    const int bm = blockIdx.x;
    const int g = lane >> 2, tg = lane & 3;

    float acc[2][5][4];
#pragma unroll
    for (int i = 0; i < 2; i++)
#pragma unroll
        for (int j = 0; j < 5; j++)
#pragma unroll
            for (int q = 0; q < 4; q++) acc[i][j][q] = 0.f;

    auto ld_stage = [&](int buf, int kt) {
        const __half* ax = g_xh + (size_t)(bm * 128) * K_TOT + kt * 32;
        char* ad = smc + buf * X_STG;
        char* bd = ad + 128 * 64;
#pragma unroll
        for (int i = 0; i < 2; i++) {
            int idx = tid + i * 256;
            int r = idx >> 2, c = idx & 3;
            CP16(smem_u32(ad + r * 64 + ((c ^ (r & 3)) << 4)), ax + (size_t)r * K_TOT + c * 8);
        }
#pragma unroll
        for (int i = 0; i < 2; i++) {
            int idx = tid + i * 256;
            if (idx < 320) {
                int r = idx >> 2, c = idx & 3;
                CP16(smem_u32(bd + r * 64 + ((c ^ (r & 3)) << 4)),
                     g_ah + (size_t)r * K_TOT + kt * 32 + c * 8);
            }
        }
    };

    ld_stage(0, 0); CPC();
    ld_stage(1, 1); CPC();
    ld_stage(2, 2); CPC();

    const int KT = K_TOT / 32;
    for (int kt = 0; kt < KT; kt++) {
        CPW(2);
        __syncthreads();
        if (kt + 3 < KT) ld_stage((kt + 3) & 3, kt + 3);
        CPC();

        const char* A = smc + (kt & 3) * X_STG;
        const char* B = A + 128 * 64;

        uint4 bq[5];
#pragma unroll
        for (int nt = 0; nt < 5; nt++) {
            int n = warpN * 40 + nt * 8 + g;
            bq[nt] = *(const uint4*)(B + n * 64 + ((tg ^ (n & 3)) << 4));
        }
#pragma unroll
        for (int mt = 0; mt < 2; mt++) {
            int r0 = warpM * 32 + mt * 16 + g;
            int sw = (tg ^ (r0 & 3)) << 4;
            uint4 a0 = *(const uint4*)(A + r0 * 64 + sw);
            uint4 a1 = *(const uint4*)(A + (r0 + 8) * 64 + sw);
#pragma unroll
            for (int nt = 0; nt < 5; nt++) {
                mma16(acc[mt][nt], a0.x, a1.x, a0.y, a1.y, bq[nt].x, bq[nt].y);
                mma16(acc[mt][nt], a0.z, a1.z, a0.w, a1.w, bq[nt].z, bq[nt].w);
            }
        }
    }

#pragma unroll
    for (int mt = 0; mt < 2; mt++)
#pragma unroll
        for (int nt = 0; nt < 5; nt++) {
            int row = bm * 128 + warpM * 32 + mt * 16 + g;
            int col = warpN * 40 + nt * 8 + tg * 2;
            *(__half2*)&g_xah[(size_t)row * XA_COLS + col] =
                __floats2half2_rn(acc[mt][nt][0], acc[mt][nt][1]);
            *(__half2*)&g_xah[(size_t)(row + 8) * XA_COLS + col] =
                __floats2half2_rn(acc[mt][nt][2], acc[mt][nt][3]);
        }
}

// ---------------------------------------------------------------------------
// Kernel 2: main fused GEMM, fp16 m16n8k16. CTA 256x128, 512 threads,
// 16 warps as 4x4 (warp 64x32) for 4 warps/SMSP latency hiding.
// 4-stage pipeline, XOR-swizzled 64B rows, permuted-K LDS.128.
// ---------------------------------------------------------------------------
#define BM 256
#define BN 128
#define STG_B 24576                 // (256+128) rows * 64 B
#define OFF_XA (4 * STG_B)          // 98304 ; XA tile 256*160B
#define OFF_BEP (OFF_XA + 256 * 160)        // 139264 ; Bep 5*128*32
#define SMEM_MAIN (OFF_BEP + NPLANE * 128 * 32)  // 159744
#define NTHR 512

__global__ void __launch_bounds__(NTHR, 1) main_kernel(
    const float* __restrict__ bias, const float* __restrict__ scales,
    float* __restrict__ out) {
    extern __shared__ char smc[];
    const int tid = threadIdx.x;
    const int lane = tid & 31, wid = tid >> 5;
    const int warpM = wid >> 2, warpN = wid & 3;   // 4 x 4 of 64x32
    const int bn = blockIdx.x, bm = blockIdx.y;
    const int g = lane >> 2, tg = lane & 3;

    float acc[4][4][4];
#pragma unroll
    for (int i = 0; i < 4; i++)
#pragma unroll
        for (int j = 0; j < 4; j++)
#pragma unroll
            for (int q = 0; q < 4; q++) acc[i][j][q] = 0.f;

    // ---- epilogue tiles: first commit group ----
    {
        const __half* xs = g_xah + (size_t)(bm * BM) * XA_COLS;
#pragma unroll
        for (int i = 0; i < 5; i++) {           // 2560 chunks
            int idx = tid + i * NTHR;
            int r = idx / 10, c = idx % 10;
            CP16(smem_u32(smc + OFF_XA + r * 160 + c * 16), xs + (size_t)r * XA_COLS + c * 8);
        }
#pragma unroll
        for (int i = 0; i < 3; i++) {           // 1280 chunks
            int idx = tid + i * NTHR;
            if (idx < 1280) {
                int p = idx >> 8, n = (idx >> 1) & 127, c = idx & 1;
                CP16(smem_u32(smc + OFF_BEP + (p * 128 + n) * 32 + c * 16),
                     g_bh + ((size_t)p * N_TOT + bn * BN + n) * RNK + c * 8);
            }
        }
    }

    auto ld_stage = [&](int buf, int kt) {
        const __half* ax = g_xh + (size_t)(bm * BM) * K_TOT + kt * 32;
        const __half* bw = g_wh + (size_t)(bn * BN) * K_TOT + kt * 32;
        char* ad = smc + buf * STG_B;
        char* bd = ad + BM * 64;
#pragma unroll
        for (int i = 0; i < 2; i++) {
            int idx = tid + i * NTHR;
            int r = idx >> 2, c = idx & 3;
            CP16(smem_u32(ad + r * 64 + ((c ^ (r & 3)) << 4)), ax + (size_t)r * K_TOT + c * 8);
        }
        {
            int r = tid >> 2, c = tid & 3;
            CP16(smem_u32(bd + r * 64 + ((c ^ (r & 3)) << 4)), bw + (size_t)r * K_TOT + c * 8);
        }
    };

    ld_stage(0, 0); CPC();    // group 0 = epi tiles + stage 0
    ld_stage(1, 1); CPC();
    ld_stage(2, 2); CPC();

    const int KT = K_TOT / 32;  // 32
    for (int kt = 0; kt < KT; kt++) {
        CPW(2);
        __syncthreads();
        if (kt + 3 < KT) ld_stage((kt + 3) & 3, kt + 3);
        CPC();

        const char* A = smc + (kt & 3) * STG_B;
        const char* B = A + BM * 64;

        uint4 bq[4];
#pragma unroll
        for (int nt = 0; nt < 4; nt++) {
            int n = warpN * 32 + nt * 8 + g;
            bq[nt] = *(const uint4*)(B + n * 64 + ((tg ^ (n & 3)) << 4));
        }
#pragma unroll
        for (int mt = 0; mt < 4; mt++) {
            int r0 = warpM * 64 + mt * 16 + g;
            int sw = (tg ^ (r0 & 3)) << 4;
            uint4 a0 = *(const uint4*)(A + r0 * 64 + sw);
            uint4 a1 = *(const uint4*)(A + (r0 + 8) * 64 + sw);
#pragma unroll
            for (int nt = 0; nt < 4; nt++)
                mma16(acc[mt][nt], a0.x, a1.x, a0.y, a1.y, bq[nt].x, bq[nt].y);
#pragma unroll
            for (int nt = 0; nt < 4; nt++)
                mma16(acc[mt][nt], a0.z, a1.z, a0.w, a1.w, bq[nt].z, bq[nt].w);
        }
    }

    CPW(0);
    __syncthreads();

    // ---- Epilogue ----
    float scl[NPLANE];
    scl[0] = 1.f;
#pragma unroll
    for (int p = 1; p < NPLANE; p++) scl[p] = __ldg(&scales[p - 1]);

#pragma unroll
    for (int nt = 0; nt < 4; nt++) {
        int c = bn * BN + warpN * 32 + nt * 8 + tg * 2;
        float b0 = __ldg(&bias[c]), b1 = __ldg(&bias[c + 1]);
#pragma unroll
        for (int mt = 0; mt < 4; mt++) {
            acc[mt][nt][0] += b0; acc[mt][nt][1] += b1;
            acc[mt][nt][2] += b0; acc[mt][nt][3] += b1;
        }
    }

    const char* XAs = smc + OFF_XA;
    const char* Bep = smc + OFF_BEP;
    const int sH = tg >> 1, sL = tg & 1;   // permuted k16 mapping

#pragma unroll
    for (int p = 0; p < NPLANE; p++) {
        float s = scl[p];
        float* op = out + (size_t)p * M_TOT * N_TOT;

        unsigned bb[4][2];
#pragma unroll
        for (int nt = 0; nt < 4; nt++) {
            int n = warpN * 32 + nt * 8 + g;
            uint4 v = *(const uint4*)(Bep + (p * 128 + n) * 32 + sL * 16);
            bb[nt][0] = sH ? v.z : v.x;
            bb[nt][1] = sH ? v.w : v.y;
        }

#pragma unroll
        for (int mt = 0; mt < 4; mt++) {
            int r0 = warpM * 64 + mt * 16 + g;
            uint4 x0 = *(const uint4*)(XAs + r0 * 160 + p * 32 + sL * 16);
            uint4 x1 = *(const uint4*)(XAs + (r0 + 8) * 160 + p * 32 + sL * 16);
            unsigned a0 = sH ? x0.z : x0.x, a2 = sH ? x0.w : x0.y;
            unsigned a1 = sH ? x1.z : x1.x, a3 = sH ? x1.w : x1.y;

            float d[4][4];
#pragma unroll
            for (int nt = 0; nt < 4; nt++) {
#pragma unroll
                for (int q = 0; q < 4; q++) d[nt][q] = 0.f;
                mma16(d[nt], a0, a1, a2, a3, bb[nt][0], bb[nt][1]);
            }

            int row = bm * BM + r0;
#pragma unroll
            for (int nt = 0; nt < 4; nt++) {
                int col = bn * BN + warpN * 32 + nt * 8 + tg * 2;
                float2 v0 = make_float2(acc[mt][nt][0] + s * d[nt][0],
                                        acc[mt][nt][1] + s * d[nt][1]);
                float2 v1 = make_float2(acc[mt][nt][2] + s * d[nt][2],
                                        acc[mt][nt][3] + s * d[nt][3]);
                __stcs((float2*)&op[(size_t)row * N_TOT + col], v0);
                __stcs((float2*)&op[(size_t)(row + 8) * N_TOT + col], v1);
            }
        }
    }
}

// ---------------------------------------------------------------------------
extern "C" void kernel_launch(void* const* d_in, const int* in_sizes, int n_in,
                              void* d_out, int out_size) {
    const float* x = (const float*)d_in[0];
    const float* W = (const float*)d_in[1];
    const float* b = (const float*)d_in[2];
    const float* A_sh = (const float*)d_in[3];
    const float* B_sh = (const float*)d_in[4];
    const float* A_tasks = (const float*)d_in[5];
    const float* B_tasks = (const float*)d_in[6];
    const float* scales = (const float*)d_in[7];
    float* out = (float*)d_out;

    cudaFuncSetAttribute(xa_kernel, cudaFuncAttributeMaxDynamicSharedMemorySize, X_SMEM);
    cudaFuncSetAttribute(main_kernel, cudaFuncAttributeMaxDynamicSharedMemorySize, SMEM_MAIN);

    cvt_x_kernel<<<(M_TOT * (K_TOT / 8)) / 256, 256>>>(x);
    cvt_w_kernel<<<(N_TOT * (K_TOT / 8)) / 256, 256>>>(W);
    cvt_a_kernel<<<(XA_COLS * K_TOT) / 256, 256>>>(A_sh, A_tasks);
    cvt_b_kernel<<<(NPLANE * N_TOT * RNK) / 256, 256>>>(B_sh, B_tasks);
    xa_kernel<<<M_TOT / 128, 256, X_SMEM>>>();
    main_kernel<<<dim3(N_TOT / BN, M_TOT / BM), NTHR, SMEM_MAIN>>>(b, scales, out);
    (void)in_sizes; (void)n_in; (void)out_size;
}

// round 13
// speedup vs baseline: 2.0487x; 1.0868x over previous
#include <cuda_runtime.h>
#include <cuda_fp16.h>
#include <cstdint>

// Problem dims
#define M_TOT 32768
#define K_TOT 1024
#define N_TOT 1024
#define RNK   16
#define NPLANE 5
#define XA_COLS 80

// ---------------- scratch ----------------
__device__ __half g_xh[(size_t)M_TOT * K_TOT];        // x in fp16
__device__ __half g_wh[(size_t)N_TOT * K_TOT];        // W in fp16
__device__ __half g_ah[(size_t)XA_COLS * K_TOT];      // [A_sh; A_tasks] fp16
__device__ __half g_bh[(size_t)NPLANE * N_TOT * RNK]; // [B_sh; B_tasks] fp16
__device__ __half g_xah[(size_t)M_TOT * XA_COLS];     // XA result fp16

__device__ __forceinline__ uint32_t smem_u32(const void* p) {
    return (uint32_t)__cvta_generic_to_shared(p);
}
#define CP16(d, s) asm volatile("cp.async.cg.shared.global [%0], [%1], 16;" ::"r"(d), "l"(s))
#define CPC() asm volatile("cp.async.commit_group;")
#define CPW(n) asm volatile("cp.async.wait_group %0;" ::"n"(n))

// fp16 mma, fp32 accum
__device__ __forceinline__ void mma16(float c[4], unsigned a0, unsigned a1, unsigned a2,
                                      unsigned a3, unsigned b0, unsigned b1) {
    asm volatile(
        "mma.sync.aligned.m16n8k16.row.col.f32.f16.f16.f32 "
        "{%0,%1,%2,%3},{%4,%5,%6,%7},{%8,%9},{%0,%1,%2,%3};"
        : "+f"(c[0]), "+f"(c[1]), "+f"(c[2]), "+f"(c[3])
        : "r"(a0), "r"(a1), "r"(a2), "r"(a3), "r"(b0), "r"(b1));
}

// ---------------------------------------------------------------------------
// Pre-convert kernels (f32 -> fp16 rn)
// ---------------------------------------------------------------------------
__device__ __forceinline__ void cvt8(const float* s, __half* d) {
    float4 v0 = *(const float4*)s;
    float4 v1 = *(const float4*)(s + 4);
    __half2 h0 = __floats2half2_rn(v0.x, v0.y), h1 = __floats2half2_rn(v0.z, v0.w);
    __half2 h2 = __floats2half2_rn(v1.x, v1.y), h3 = __floats2half2_rn(v1.z, v1.w);
    uint4 o;
    o.x = *(uint32_t*)&h0; o.y = *(uint32_t*)&h1;
    o.z = *(uint32_t*)&h2; o.w = *(uint32_t*)&h3;
    *(uint4*)d = o;
}
__global__ void cvt_x_kernel(const float* __restrict__ x) {
    size_t i = ((size_t)blockIdx.x * 256 + threadIdx.x) * 8;
    cvt8(x + i, g_xh + i);
}
__global__ void cvt_w_kernel(const float* __restrict__ W) {
    size_t i = ((size_t)blockIdx.x * 256 + threadIdx.x) * 8;
    cvt8(W + i, g_wh + i);
}
__global__ void cvt_ab_kernel(const float* __restrict__ A_sh,
                              const float* __restrict__ A_tasks,
                              const float* __restrict__ B_sh,
                              const float* __restrict__ B_tasks) {
    int i = blockIdx.x * 256 + threadIdx.x;   // 640 blocks -> 163840
    if (i < XA_COLS * K_TOT) {
        float v = (i < RNK * K_TOT) ? A_sh[i] : A_tasks[i - RNK * K_TOT];
        g_ah[i] = __float2half_rn(v);
    } else {
        int j = i - XA_COLS * K_TOT;
        float v = (j < N_TOT * RNK) ? B_sh[j] : B_tasks[j - N_TOT * RNK];
        g_bh[j] = __float2half_rn(v);
    }
}

// ---------------------------------------------------------------------------
// Kernel 1: XA = x @ [A_sh; A_tasks]^T   fp16 m16n8k16. CTA 128 rows.
// 8 warps as 4x2 (warp 32x40). 4-stage pipeline, 64B swizzled rows, occ 2.
// ---------------------------------------------------------------------------
#define X_STG 13312   // (128 + 80) rows * 64 B
#define X_SMEM (4 * X_STG)

__global__ void __launch_bounds__(256, 2) xa_kernel() {
    extern __shared__ char smc[];
    const int tid = threadIdx.x;
    const int lane = tid & 31, wid = tid >> 5;
    const int warpM = wid >> 1, warpN = wid & 1;
    const int bm = blockIdx.x;
    const int g = lane >> 2, tg = lane & 3;

    float acc[2][5][4];
#pragma unroll
    for (int i = 0; i < 2; i++)
#pragma unroll
        for (int j = 0; j < 5; j++)
#pragma unroll
            for (int q = 0; q < 4; q++) acc[i][j][q] = 0.f;

    auto ld_stage = [&](int buf, int kt) {
        const __half* ax = g_xh + (size_t)(bm * 128) * K_TOT + kt * 32;
        char* ad = smc + buf * X_STG;
        char* bd = ad + 128 * 64;
#pragma unroll
        for (int i = 0; i < 2; i++) {
            int idx = tid + i * 256;
            int r = idx >> 2, c = idx & 3;
            CP16(smem_u32(ad + r * 64 + ((c ^ (r & 3)) << 4)), ax + (size_t)r * K_TOT + c * 8);
        }
#pragma unroll
        for (int i = 0; i < 2; i++) {
            int idx = tid + i * 256;
            if (idx < 320) {
                int r = idx >> 2, c = idx & 3;
                CP16(smem_u32(bd + r * 64 + ((c ^ (r & 3)) << 4)),
                     g_ah + (size_t)r * K_TOT + kt * 32 + c * 8);
            }
        }
    };

    ld_stage(0, 0); CPC();
    ld_stage(1, 1); CPC();
    ld_stage(2, 2); CPC();

    const int KT = K_TOT / 32;
    for (int kt = 0; kt < KT; kt++) {
        CPW(2);
        __syncthreads();
        if (kt + 3 < KT) ld_stage((kt + 3) & 3, kt + 3);
        CPC();

        const char* A = smc + (kt & 3) * X_STG;
        const char* B = A + 128 * 64;

        uint4 bq[5];
#pragma unroll
        for (int nt = 0; nt < 5; nt++) {
            int n = warpN * 40 + nt * 8 + g;
            bq[nt] = *(const uint4*)(B + n * 64 + ((tg ^ (n & 3)) << 4));
        }
#pragma unroll
        for (int mt = 0; mt < 2; mt++) {
            int r0 = warpM * 32 + mt * 16 + g;
            int sw = (tg ^ (r0 & 3)) << 4;
            uint4 a0 = *(const uint4*)(A + r0 * 64 + sw);
            uint4 a1 = *(const uint4*)(A + (r0 + 8) * 64 + sw);
#pragma unroll
            for (int nt = 0; nt < 5; nt++) {
                mma16(acc[mt][nt], a0.x, a1.x, a0.y, a1.y, bq[nt].x, bq[nt].y);
                mma16(acc[mt][nt], a0.z, a1.z, a0.w, a1.w, bq[nt].z, bq[nt].w);
            }
        }
    }

#pragma unroll
    for (int mt = 0; mt < 2; mt++)
#pragma unroll
        for (int nt = 0; nt < 5; nt++) {
            int row = bm * 128 + warpM * 32 + mt * 16 + g;
            int col = warpN * 40 + nt * 8 + tg * 2;
            *(__half2*)&g_xah[(size_t)row * XA_COLS + col] =
                __floats2half2_rn(acc[mt][nt][0], acc[mt][nt][1]);
            *(__half2*)&g_xah[(size_t)(row + 8) * XA_COLS + col] =
                __floats2half2_rn(acc[mt][nt][2], acc[mt][nt][3]);
        }
}

// ---------------------------------------------------------------------------
// Kernel 2: main fused GEMM, fp16 m16n8k16. CTA 128x128, 256 threads,
// 8 warps as 2x4 (warp 64x32). OCCUPANCY 2: one CTA's store epilogue
// overlaps the co-resident CTA's mainloop. 4-stage pipeline, 64B swizzle.
// ---------------------------------------------------------------------------
#define BM 128
#define BN 128
#define STG_B 16384                 // (128+128) rows * 64 B
#define OFF_XA (4 * STG_B)          // 65536 ; XA tile 128*160B = 20480
#define OFF_BEP (OFF_XA + BM * 160)         // 86016 ; Bep 5*128*32 = 20480
#define SMEM_MAIN (OFF_BEP + NPLANE * 128 * 32)  // 106496
#define NTHR 256

__global__ void __launch_bounds__(NTHR, 2) main_kernel(
    const float* __restrict__ bias, const float* __restrict__ scales,
    float* __restrict__ out) {
    extern __shared__ char smc[];
    const int tid = threadIdx.x;
    const int lane = tid & 31, wid = tid >> 5;
    const int warpM = wid >> 2, warpN = wid & 3;   // 2 x 4 of 64x32
    const int bn = blockIdx.x, bm = blockIdx.y;
    const int g = lane >> 2, tg = lane & 3;

    float acc[4][4][4];
#pragma unroll
    for (int i = 0; i < 4; i++)
#pragma unroll
        for (int j = 0; j < 4; j++)
#pragma unroll
            for (int q = 0; q < 4; q++) acc[i][j][q] = 0.f;

    // ---- epilogue tiles: first commit group ----
    {
        const __half* xs = g_xah + (size_t)(bm * BM) * XA_COLS;
#pragma unroll
        for (int i = 0; i < 5; i++) {           // 1280 chunks
            int idx = tid + i * NTHR;
            int r = idx / 10, c = idx % 10;
            CP16(smem_u32(smc + OFF_XA + r * 160 + c * 16), xs + (size_t)r * XA_COLS + c * 8);
        }
#pragma unroll
        for (int i = 0; i < 5; i++) {           // 1280 chunks
            int idx = tid + i * NTHR;
            int p = idx >> 8, n = (idx >> 1) & 127, c = idx & 1;
            CP16(smem_u32(smc + OFF_BEP + (p * 128 + n) * 32 + c * 16),
                 g_bh + ((size_t)p * N_TOT + bn * BN + n) * RNK + c * 8);
        }
    }

    auto ld_stage = [&](int buf, int kt) {
        const __half* ax = g_xh + (size_t)(bm * BM) * K_TOT + kt * 32;
        const __half* bw = g_wh + (size_t)(bn * BN) * K_TOT + kt * 32;
        char* ad = smc + buf * STG_B;
        char* bd = ad + BM * 64;
#pragma unroll
        for (int i = 0; i < 2; i++) {
            int idx = tid + i * NTHR;
            int r = idx >> 2, c = idx & 3;
            CP16(smem_u32(ad + r * 64 + ((c ^ (r & 3)) << 4)), ax + (size_t)r * K_TOT + c * 8);
        }
#pragma unroll
        for (int i = 0; i < 2; i++) {
            int idx = tid + i * NTHR;
            int r = idx >> 2, c = idx & 3;
            CP16(smem_u32(bd + r * 64 + ((c ^ (r & 3)) << 4)), bw + (size_t)r * K_TOT + c * 8);
        }
    };

    ld_stage(0, 0); CPC();    // group 0 = epi tiles + stage 0
    ld_stage(1, 1); CPC();
    ld_stage(2, 2); CPC();

    const int KT = K_TOT / 32;  // 32
    for (int kt = 0; kt < KT; kt++) {
        CPW(2);
        __syncthreads();
        if (kt + 3 < KT) ld_stage((kt + 3) & 3, kt + 3);
        CPC();

        const char* A = smc + (kt & 3) * STG_B;
        const char* B = A + BM * 64;

        uint4 bq[4];
#pragma unroll
        for (int nt = 0; nt < 4; nt++) {
            int n = warpN * 32 + nt * 8 + g;
            bq[nt] = *(const uint4*)(B + n * 64 + ((tg ^ (n & 3)) << 4));
        }
#pragma unroll
        for (int mt = 0; mt < 4; mt++) {
            int r0 = warpM * 64 + mt * 16 + g;
            int sw = (tg ^ (r0 & 3)) << 4;
            uint4 a0 = *(const uint4*)(A + r0 * 64 + sw);
            uint4 a1 = *(const uint4*)(A + (r0 + 8) * 64 + sw);
#pragma unroll
            for (int nt = 0; nt < 4; nt++)
                mma16(acc[mt][nt], a0.x, a1.x, a0.y, a1.y, bq[nt].x, bq[nt].y);
#pragma unroll
            for (int nt = 0; nt < 4; nt++)
                mma16(acc[mt][nt], a0.z, a1.z, a0.w, a1.w, bq[nt].z, bq[nt].w);
        }
    }

    CPW(0);
    __syncthreads();

    // ---- Epilogue (overlaps co-resident CTA's mainloop) ----
    float scl[NPLANE];
    scl[0] = 1.f;
#pragma unroll
    for (int p = 1; p < NPLANE; p++) scl[p] = __ldg(&scales[p - 1]);

#pragma unroll
    for (int nt = 0; nt < 4; nt++) {
        int c = bn * BN + warpN * 32 + nt * 8 + tg * 2;
        float b0 = __ldg(&bias[c]), b1 = __ldg(&bias[c + 1]);
#pragma unroll
        for (int mt = 0; mt < 4; mt++) {
            acc[mt][nt][0] += b0; acc[mt][nt][1] += b1;
            acc[mt][nt][2] += b0; acc[mt][nt][3] += b1;
        }
    }

    const char* XAs = smc + OFF_XA;
    const char* Bep = smc + OFF_BEP;
    const int sH = tg >> 1, sL = tg & 1;   // permuted k16 mapping

#pragma unroll
    for (int p = 0; p < NPLANE; p++) {
        float s = scl[p];
        float* op = out + (size_t)p * M_TOT * N_TOT;

        unsigned bb[4][2];
#pragma unroll
        for (int nt = 0; nt < 4; nt++) {
            int n = warpN * 32 + nt * 8 + g;
            uint4 v = *(const uint4*)(Bep + (p * 128 + n) * 32 + sL * 16);
            bb[nt][0] = sH ? v.z : v.x;
            bb[nt][1] = sH ? v.w : v.y;
        }

#pragma unroll
        for (int mt = 0; mt < 4; mt++) {
            int r0 = warpM * 64 + mt * 16 + g;
            uint4 x0 = *(const uint4*)(XAs + r0 * 160 + p * 32 + sL * 16);
            uint4 x1 = *(const uint4*)(XAs + (r0 + 8) * 160 + p * 32 + sL * 16);
            unsigned a0 = sH ? x0.z : x0.x, a2 = sH ? x0.w : x0.y;
            unsigned a1 = sH ? x1.z : x1.x, a3 = sH ? x1.w : x1.y;

            float d[4][4];
#pragma unroll
            for (int nt = 0; nt < 4; nt++) {
#pragma unroll
                for (int q = 0; q < 4; q++) d[nt][q] = 0.f;
                mma16(d[nt], a0, a1, a2, a3, bb[nt][0], bb[nt][1]);
            }

            int row = bm * BM + r0;
#pragma unroll
            for (int nt = 0; nt < 4; nt++) {
                int col = bn * BN + warpN * 32 + nt * 8 + tg * 2;
                float2 v0 = make_float2(acc[mt][nt][0] + s * d[nt][0],
                                        acc[mt][nt][1] + s * d[nt][1]);
                float2 v1 = make_float2(acc[mt][nt][2] + s * d[nt][2],
                                        acc[mt][nt][3] + s * d[nt][3]);
                __stcs((float2*)&op[(size_t)row * N_TOT + col], v0);
                __stcs((float2*)&op[(size_t)(row + 8) * N_TOT + col], v1);
            }
        }
    }
}

// ---------------------------------------------------------------------------
extern "C" void kernel_launch(void* const* d_in, const int* in_sizes, int n_in,
                              void* d_out, int out_size) {
    const float* x = (const float*)d_in[0];
    const float* W = (const float*)d_in[1];
    const float* b = (const float*)d_in[2];
    const float* A_sh = (const float*)d_in[3];
    const float* B_sh = (const float*)d_in[4];
    const float* A_tasks = (const float*)d_in[5];
    const float* B_tasks = (const float*)d_in[6];
    const float* scales = (const float*)d_in[7];
    float* out = (float*)d_out;

    cudaFuncSetAttribute(xa_kernel, cudaFuncAttributeMaxDynamicSharedMemorySize, X_SMEM);
    cudaFuncSetAttribute(main_kernel, cudaFuncAttributeMaxDynamicSharedMemorySize, SMEM_MAIN);

    cvt_x_kernel<<<(M_TOT * (K_TOT / 8)) / 256, 256>>>(x);
    cvt_w_kernel<<<(N_TOT * (K_TOT / 8)) / 256, 256>>>(W);
    cvt_ab_kernel<<<(XA_COLS * K_TOT + NPLANE * N_TOT * RNK) / 256, 256>>>(A_sh, A_tasks,
                                                                            B_sh, B_tasks);
    xa_kernel<<<M_TOT / 128, 256, X_SMEM>>>();
    main_kernel<<<dim3(N_TOT / BN, M_TOT / BM), NTHR, SMEM_MAIN>>>(b, scales, out);
    (void)in_sizes; (void)n_in; (void)out_size;
}

// round 14
// speedup vs baseline: 2.1281x; 1.0388x over previous
#include <cuda_runtime.h>
#include <cuda_fp16.h>
#include <cstdint>

// Problem dims
#define M_TOT 32768
#define K_TOT 1024
#define N_TOT 1024
#define RNK   16
#define NPLANE 5
#define XA_COLS 80

// ---------------- scratch ----------------
__device__ __half g_xh[(size_t)M_TOT * K_TOT];        // x in fp16 (written by xa_kernel)
__device__ __half g_wh[(size_t)N_TOT * K_TOT];        // W in fp16
__device__ __half g_ah[(size_t)XA_COLS * K_TOT];      // [A_sh; A_tasks] fp16
__device__ __half g_bh[(size_t)NPLANE * N_TOT * RNK]; // [B_sh; B_tasks] fp16
__device__ __half g_xah[(size_t)M_TOT * XA_COLS];     // XA result fp16

__device__ __forceinline__ uint32_t smem_u32(const void* p) {
    return (uint32_t)__cvta_generic_to_shared(p);
}
#define CP16(d, s) asm volatile("cp.async.cg.shared.global [%0], [%1], 16;" ::"r"(d), "l"(s))
#define CPC() asm volatile("cp.async.commit_group;")
#define CPW(n) asm volatile("cp.async.wait_group %0;" ::"n"(n))

// fp16 mma, fp32 accum
__device__ __forceinline__ void mma16(float c[4], unsigned a0, unsigned a1, unsigned a2,
                                      unsigned a3, unsigned b0, unsigned b1) {
    asm volatile(
        "mma.sync.aligned.m16n8k16.row.col.f32.f16.f16.f32 "
        "{%0,%1,%2,%3},{%4,%5,%6,%7},{%8,%9},{%0,%1,%2,%3};"
        : "+f"(c[0]), "+f"(c[1]), "+f"(c[2]), "+f"(c[3])
        : "r"(a0), "r"(a1), "r"(a2), "r"(a3), "r"(b0), "r"(b1));
}

// ---------------------------------------------------------------------------
// One fused conversion kernel for W, A, B (f32 -> fp16 rn)
// grid: 512 (W vec8) + 640 (A/B scalar) = 1152 blocks
// ---------------------------------------------------------------------------
__global__ void cvt_wab_kernel(const float* __restrict__ W,
                               const float* __restrict__ A_sh,
                               const float* __restrict__ A_tasks,
                               const float* __restrict__ B_sh,
                               const float* __restrict__ B_tasks) {
    int blk = blockIdx.x;
    if (blk < 512) {
        size_t i = ((size_t)blk * 256 + threadIdx.x) * 8;
        float4 v0 = *(const float4*)(W + i);
        float4 v1 = *(const float4*)(W + i + 4);
        __half2 h0 = __floats2half2_rn(v0.x, v0.y), h1 = __floats2half2_rn(v0.z, v0.w);
        __half2 h2 = __floats2half2_rn(v1.x, v1.y), h3 = __floats2half2_rn(v1.z, v1.w);
        uint4 o;
        o.x = *(uint32_t*)&h0; o.y = *(uint32_t*)&h1;
        o.z = *(uint32_t*)&h2; o.w = *(uint32_t*)&h3;
        *(uint4*)(g_wh + i) = o;
    } else {
        int i = (blk - 512) * 256 + threadIdx.x;   // 0 .. 163839
        if (i < XA_COLS * K_TOT) {
            float v = (i < RNK * K_TOT) ? A_sh[i] : A_tasks[i - RNK * K_TOT];
            g_ah[i] = __float2half_rn(v);
        } else {
            int j = i - XA_COLS * K_TOT;
            float v = (j < N_TOT * RNK) ? B_sh[j] : B_tasks[j - N_TOT * RNK];
            g_bh[j] = __float2half_rn(v);
        }
    }
}

// ---------------------------------------------------------------------------
// Kernel 1: XA = x @ [A_sh; A_tasks]^T,  AND produce g_xh (x in fp16).
// Reads f32 x. CTA covers 64 rows; 8 warps as 4x2 (warp 16x40); occ 2.
// A stage: 64 rows x 128B f32 (swizzled); B stage: 80 rows x 64B fp16.
// After each k-tile's mma, the f32 stage is converted and stored to g_xh.
// ---------------------------------------------------------------------------
#define X_BM 64
#define X_ASTG 8192                  // 64 * 128
#define X_STG (X_ASTG + 5120)        // + 80 * 64 = 13312
#define X_SMEM (4 * X_STG)           // 53248

__global__ void __launch_bounds__(256, 2) xa_kernel(const float* __restrict__ x) {
    extern __shared__ char smc[];
    const int tid = threadIdx.x;
    const int lane = tid & 31, wid = tid >> 5;
    const int warpM = wid >> 1, warpN = wid & 1;   // 4 x 2, warp 16x40
    const int bm = blockIdx.x;
    const int g = lane >> 2, tg = lane & 3;

    float acc[5][4];
#pragma unroll
    for (int j = 0; j < 5; j++)
#pragma unroll
        for (int q = 0; q < 4; q++) acc[j][q] = 0.f;

    auto ld_stage = [&](int buf, int kt) {
        const float* ax = x + (size_t)(bm * X_BM) * K_TOT + kt * 32;
        char* ad = smc + buf * X_STG;
        char* bd = ad + X_ASTG;
        // A: f32, 128B rows, 8 chunks, XOR-8 swizzle (conflict-free per-phase)
#pragma unroll
        for (int i = 0; i < 2; i++) {
            int idx = tid + i * 256;
            int r = idx >> 3, c = idx & 7;
            CP16(smem_u32(ad + r * 128 + ((c ^ (r & 7)) << 4)), ax + (size_t)r * K_TOT + c * 4);
        }
        // B: fp16, 64B rows, XOR-4 swizzle
#pragma unroll
        for (int i = 0; i < 2; i++) {
            int idx = tid + i * 256;
            if (idx < 320) {
                int r = idx >> 2, c = idx & 3;
                CP16(smem_u32(bd + r * 64 + ((c ^ (r & 3)) << 4)),
                     g_ah + (size_t)r * K_TOT + kt * 32 + c * 8);
            }
        }
    };

    ld_stage(0, 0); CPC();
    ld_stage(1, 1); CPC();
    ld_stage(2, 2); CPC();

    const int wr_r = tid >> 2, wr_c = tid & 3;   // writeback mapping (row, 32B chunk)

    const int KT = K_TOT / 32;
    for (int kt = 0; kt < KT; kt++) {
        CPW(2);
        __syncthreads();
        if (kt + 3 < KT) ld_stage((kt + 3) & 3, kt + 3);
        CPC();

        const char* A = smc + (kt & 3) * X_STG;
        const char* B = A + X_ASTG;

        uint4 bq[5];
#pragma unroll
        for (int nt = 0; nt < 5; nt++) {
            int n = warpN * 40 + nt * 8 + g;
            bq[nt] = *(const uint4*)(B + n * 64 + ((tg ^ (n & 3)) << 4));
        }
        // A fragments: f32 -> fp16 in registers (rows r0 and r0+8)
        int r0 = warpM * 16 + g;
        unsigned h0[4], h1[4];
        {
            int c0 = (2 * tg) ^ (r0 & 7), c1 = (2 * tg + 1) ^ (r0 & 7);
            float4 f0 = *(const float4*)(A + r0 * 128 + (c0 << 4));
            float4 f1 = *(const float4*)(A + r0 * 128 + (c1 << 4));
            __half2 t0 = __floats2half2_rn(f0.x, f0.y), t1 = __floats2half2_rn(f0.z, f0.w);
            __half2 t2 = __floats2half2_rn(f1.x, f1.y), t3 = __floats2half2_rn(f1.z, f1.w);
            h0[0] = *(unsigned*)&t0; h0[1] = *(unsigned*)&t1;
            h0[2] = *(unsigned*)&t2; h0[3] = *(unsigned*)&t3;
            int r1 = r0 + 8;
            int d0 = (2 * tg) ^ (r1 & 7), d1 = (2 * tg + 1) ^ (r1 & 7);
            float4 g0 = *(const float4*)(A + r1 * 128 + (d0 << 4));
            float4 g1 = *(const float4*)(A + r1 * 128 + (d1 << 4));
            __half2 u0 = __floats2half2_rn(g0.x, g0.y), u1 = __floats2half2_rn(g0.z, g0.w);
            __half2 u2 = __floats2half2_rn(g1.x, g1.y), u3 = __floats2half2_rn(g1.z, g1.w);
            h1[0] = *(unsigned*)&u0; h1[1] = *(unsigned*)&u1;
            h1[2] = *(unsigned*)&u2; h1[3] = *(unsigned*)&u3;
        }
#pragma unroll
        for (int nt = 0; nt < 5; nt++) {
            mma16(acc[nt], h0[0], h1[0], h0[1], h1[1], bq[nt].x, bq[nt].y);
            mma16(acc[nt], h0[2], h1[2], h0[3], h1[3], bq[nt].z, bq[nt].w);
        }

        // ---- writeback: convert this f32 stage to fp16 -> g_xh ----
        {
            int c0 = (2 * wr_c) ^ (wr_r & 7), c1 = (2 * wr_c + 1) ^ (wr_r & 7);
            float4 f0 = *(const float4*)(A + wr_r * 128 + (c0 << 4));
            float4 f1 = *(const float4*)(A + wr_r * 128 + (c1 << 4));
            __half2 t0 = __floats2half2_rn(f0.x, f0.y), t1 = __floats2half2_rn(f0.z, f0.w);
            __half2 t2 = __floats2half2_rn(f1.x, f1.y), t3 = __floats2half2_rn(f1.z, f1.w);
            uint4 o;
            o.x = *(unsigned*)&t0; o.y = *(unsigned*)&t1;
            o.z = *(unsigned*)&t2; o.w = *(unsigned*)&t3;
            *(uint4*)(g_xh + (size_t)(bm * X_BM + wr_r) * K_TOT + kt * 32 + wr_c * 8) = o;
        }
    }

#pragma unroll
    for (int nt = 0; nt < 5; nt++) {
        int row = bm * X_BM + warpM * 16 + g;
        int col = warpN * 40 + nt * 8 + tg * 2;
        *(__half2*)&g_xah[(size_t)row * XA_COLS + col] =
            __floats2half2_rn(acc[nt][0], acc[nt][1]);
        *(__half2*)&g_xah[(size_t)(row + 8) * XA_COLS + col] =
            __floats2half2_rn(acc[nt][2], acc[nt][3]);
    }
}

// ---------------------------------------------------------------------------
// Kernel 2: main fused GEMM, fp16 m16n8k16. CTA 128x128, 256 threads,
// 8 warps as 2x4 (warp 64x32), occupancy 2. 4-stage pipeline, 64B swizzle.
// ---------------------------------------------------------------------------
#define BM 128
#define BN 128
#define STG_B 16384                 // (128+128) rows * 64 B
#define OFF_XA (4 * STG_B)          // 65536 ; XA tile 128*160B = 20480
#define OFF_BEP (OFF_XA + BM * 160)         // 86016 ; Bep 5*128*32 = 20480
#define SMEM_MAIN (OFF_BEP + NPLANE * 128 * 32)  // 106496
#define NTHR 256

__global__ void __launch_bounds__(NTHR, 2) main_kernel(
    const float* __restrict__ bias, const float* __restrict__ scales,
    float* __restrict__ out) {
    extern __shared__ char smc[];
    const int tid = threadIdx.x;
    const int lane = tid & 31, wid = tid >> 5;
    const int warpM = wid >> 2, warpN = wid & 3;   // 2 x 4 of 64x32
    const int bn = blockIdx.x, bm = blockIdx.y;
    const int g = lane >> 2, tg = lane & 3;

    float acc[4][4][4];
#pragma unroll
    for (int i = 0; i < 4; i++)
#pragma unroll
        for (int j = 0; j < 4; j++)
#pragma unroll
            for (int q = 0; q < 4; q++) acc[i][j][q] = 0.f;

    auto ld_stage = [&](int buf, int kt) {
        const __half* ax = g_xh + (size_t)(bm * BM) * K_TOT + kt * 32;
        const __half* bw = g_wh + (size_t)(bn * BN) * K_TOT + kt * 32;
        char* ad = smc + buf * STG_B;
        char* bd = ad + BM * 64;
#pragma unroll
        for (int i = 0; i < 2; i++) {
            int idx = tid + i * NTHR;
            int r = idx >> 2, c = idx & 3;
            CP16(smem_u32(ad + r * 64 + ((c ^ (r & 3)) << 4)), ax + (size_t)r * K_TOT + c * 8);
        }
#pragma unroll
        for (int i = 0; i < 2; i++) {
            int idx = tid + i * NTHR;
            int r = idx >> 2, c = idx & 3;
            CP16(smem_u32(bd + r * 64 + ((c ^ (r & 3)) << 4)), bw + (size_t)r * K_TOT + c * 8);
        }
    };

    // Prologue: stages first (critical path), epilogue tiles folded into group 2.
    ld_stage(0, 0); CPC();
    ld_stage(1, 1); CPC();
    ld_stage(2, 2);
    {
        const __half* xs = g_xah + (size_t)(bm * BM) * XA_COLS;
#pragma unroll
        for (int i = 0; i < 5; i++) {           // 1280 chunks XA
            int idx = tid + i * NTHR;
            int r = idx / 10, c = idx % 10;
            CP16(smem_u32(smc + OFF_XA + r * 160 + c * 16), xs + (size_t)r * XA_COLS + c * 8);
        }
#pragma unroll
        for (int i = 0; i < 5; i++) {           // 1280 chunks Bep
            int idx = tid + i * NTHR;
            int p = idx >> 8, n = (idx >> 1) & 127, c = idx & 1;
            CP16(smem_u32(smc + OFF_BEP + (p * 128 + n) * 32 + c * 16),
                 g_bh + ((size_t)p * N_TOT + bn * BN + n) * RNK + c * 8);
        }
    }
    CPC();

    const int KT = K_TOT / 32;  // 32
    for (int kt = 0; kt < KT; kt++) {
        CPW(2);
        __syncthreads();
        if (kt + 3 < KT) ld_stage((kt + 3) & 3, kt + 3);
        CPC();

        const char* A = smc + (kt & 3) * STG_B;
        const char* B = A + BM * 64;

        uint4 bq[4];
#pragma unroll
        for (int nt = 0; nt < 4; nt++) {
            int n = warpN * 32 + nt * 8 + g;
            bq[nt] = *(const uint4*)(B + n * 64 + ((tg ^ (n & 3)) << 4));
        }
#pragma unroll
        for (int mt = 0; mt < 4; mt++) {
            int r0 = warpM * 64 + mt * 16 + g;
            int sw = (tg ^ (r0 & 3)) << 4;
            uint4 a0 = *(const uint4*)(A + r0 * 64 + sw);
            uint4 a1 = *(const uint4*)(A + (r0 + 8) * 64 + sw);
#pragma unroll
            for (int nt = 0; nt < 4; nt++)
                mma16(acc[mt][nt], a0.x, a1.x, a0.y, a1.y, bq[nt].x, bq[nt].y);
#pragma unroll
            for (int nt = 0; nt < 4; nt++)
                mma16(acc[mt][nt], a0.z, a1.z, a0.w, a1.w, bq[nt].z, bq[nt].w);
        }
    }

    // hoist bias/scales before the pipeline drain
    float scl[NPLANE];
    scl[0] = 1.f;
#pragma unroll
    for (int p = 1; p < NPLANE; p++) scl[p] = __ldg(&scales[p - 1]);
    float bv0[4], bv1[4];
#pragma unroll
    for (int nt = 0; nt < 4; nt++) {
        int c = bn * BN + warpN * 32 + nt * 8 + tg * 2;
        bv0[nt] = __ldg(&bias[c]);
        bv1[nt] = __ldg(&bias[c + 1]);
    }

    CPW(0);
    __syncthreads();

#pragma unroll
    for (int nt = 0; nt < 4; nt++)
#pragma unroll
        for (int mt = 0; mt < 4; mt++) {
            acc[mt][nt][0] += bv0[nt]; acc[mt][nt][1] += bv1[nt];
            acc[mt][nt][2] += bv0[nt]; acc[mt][nt][3] += bv1[nt];
        }

    const char* XAs = smc + OFF_XA;
    const char* Bep = smc + OFF_BEP;
    const int sH = tg >> 1, sL = tg & 1;   // permuted k16 mapping

#pragma unroll
    for (int p = 0; p < NPLANE; p++) {
        float s = scl[p];
        float* op = out + (size_t)p * M_TOT * N_TOT;

        unsigned bb[4][2];
#pragma unroll
        for (int nt = 0; nt < 4; nt++) {
            int n = warpN * 32 + nt * 8 + g;
            uint4 v = *(const uint4*)(Bep + (p * 128 + n) * 32 + sL * 16);
            bb[nt][0] = sH ? v.z : v.x;
            bb[nt][1] = sH ? v.w : v.y;
        }

#pragma unroll
        for (int mt = 0; mt < 4; mt++) {
            int r0 = warpM * 64 + mt * 16 + g;
            uint4 x0 = *(const uint4*)(XAs + r0 * 160 + p * 32 + sL * 16);
            uint4 x1 = *(const uint4*)(XAs + (r0 + 8) * 160 + p * 32 + sL * 16);
            unsigned a0 = sH ? x0.z : x0.x, a2 = sH ? x0.w : x0.y;
            unsigned a1 = sH ? x1.z : x1.x, a3 = sH ? x1.w : x1.y;

            float d[4][4];
#pragma unroll
            for (int nt = 0; nt < 4; nt++) {
#pragma unroll
                for (int q = 0; q < 4; q++) d[nt][q] = 0.f;
                mma16(d[nt], a0, a1, a2, a3, bb[nt][0], bb[nt][1]);
            }

            int row = bm * BM + r0;
#pragma unroll
            for (int nt = 0; nt < 4; nt++) {
                int col = bn * BN + warpN * 32 + nt * 8 + tg * 2;
                float2 v0 = make_float2(acc[mt][nt][0] + s * d[nt][0],
                                        acc[mt][nt][1] + s * d[nt][1]);
                float2 v1 = make_float2(acc[mt][nt][2] + s * d[nt][2],
                                        acc[mt][nt][3] + s * d[nt][3]);
                __stcs((float2*)&op[(size_t)row * N_TOT + col], v0);
                __stcs((float2*)&op[(size_t)(row + 8) * N_TOT + col], v1);
            }
        }
    }
}

// ---------------------------------------------------------------------------
extern "C" void kernel_launch(void* const* d_in, const int* in_sizes, int n_in,
                              void* d_out, int out_size) {
    const float* x = (const float*)d_in[0];
    const float* W = (const float*)d_in[1];
    const float* b = (const float*)d_in[2];
    const float* A_sh = (const float*)d_in[3];
    const float* B_sh = (const float*)d_in[4];
    const float* A_tasks = (const float*)d_in[5];
    const float* B_tasks = (const float*)d_in[6];
    const float* scales = (const float*)d_in[7];
    float* out = (float*)d_out;

    cudaFuncSetAttribute(xa_kernel, cudaFuncAttributeMaxDynamicSharedMemorySize, X_SMEM);
    cudaFuncSetAttribute(main_kernel, cudaFuncAttributeMaxDynamicSharedMemorySize, SMEM_MAIN);

    cvt_wab_kernel<<<1152, 256>>>(W, A_sh, A_tasks, B_sh, B_tasks);
    xa_kernel<<<M_TOT / X_BM, 256, X_SMEM>>>(x);
    main_kernel<<<dim3(N_TOT / BN, M_TOT / BM), NTHR, SMEM_MAIN>>>(b, scales, out);
    (void)in_sizes; (void)n_in; (void)out_size;
}